// round 15
// baseline (speedup 1.0000x reference)
#include <cuda_runtime.h>
#include <cuda_bf16.h>
#include <cstdint>
#include <math.h>

#define Dm    256
#define NMAX  32768
#define NEMAX 1000000
#define NTMAX 65536
#define KSLOT 32
#define RDm   512
#define PS    1792   // packed row stride: Q2|K2|Qm|Q3|K3
#define OQ2   0
#define OK2   256
#define OQm   512
#define OQ3   768
#define OK3   1280

typedef __nv_bfloat16 bf16;
typedef __nv_bfloat162 bf162;

// ---------------- static device scratch ----------------
__device__ __align__(16) bf16  g_Gh[(size_t)NMAX * Dm];
__device__ __align__(16) bf16  g_Ph[(size_t)NMAX * PS];
__device__ __align__(16) bf16  g_gPh[(size_t)NMAX * PS];
__device__ __align__(16) bf16  g_Wfh[(size_t)Dm * PS];   // [k=256][n=1792]
__device__ __align__(16) bf16  g_Wbh[(size_t)PS * Dm];   // [n=1792][k=256]
__device__ __align__(16) float g_gG[(size_t)NMAX * Dm];
__device__ float g_mu[NMAX];
__device__ float g_rstd[NMAX];
__device__ float g_Km[KSLOT * Dm];
__device__ float g_S2[NEMAX];   // exp(s2) per edge
__device__ float g_S3[NTMAX];   // exp(s3) per triangle
__device__ float g_ES3[NMAX];
__device__ float g_LSE2[NMAX];  // cw2 / sum(exp(s2))
__device__ float g_LSE3[NMAX];  // 1 / sum(exp(s3))
__device__ double g_EL2, g_EL3, g_ELm;
// CSR for edges
__device__ int  g_cntc[NMAX], g_cntu[NMAX];
__device__ int  g_ofsc[NMAX + 1], g_ofsu[NMAX + 1];
__device__ int  g_posc[NMAX], g_posu[NMAX];
__device__ int2 g_e2c[NEMAX];
__device__ int2 g_e2u[NEMAX];
// CSR for triangles (all 3 roles per node)
__device__ int  g_cnt3[NMAX];
__device__ int  g_ofs3[NMAX + 1];
__device__ int  g_pos3[NMAX];
__device__ int4 g_e3[3 * NTMAX];   // (a, b, tri, tau | role<<1)

struct Consts {
    float sb2, sb3, sbm;
    float cw2, cw3, cwm;
    float ce2, ce3, cem;
    float step;
};
__device__ Consts g_c;

// ---------------- generic helpers ----------------
__device__ __forceinline__ float spf(float x) { return x > 20.f ? x : log1pf(expf(x)); }

__device__ __forceinline__ float2 h2f(unsigned u) {
    bf162 h = *(bf162*)&u;
    return __bfloat1622float2(h);
}
__device__ __forceinline__ unsigned f2h(float a, float b) {
    bf162 h = __floats2bfloat162_rn(a, b);
    return *(unsigned*)&h;
}
__device__ __forceinline__ void unpack8(uint4 v, float* f) {
    float2 p;
    p = h2f(v.x); f[0] = p.x; f[1] = p.y;
    p = h2f(v.y); f[2] = p.x; f[3] = p.y;
    p = h2f(v.z); f[4] = p.x; f[5] = p.y;
    p = h2f(v.w); f[6] = p.x; f[7] = p.y;
}

__device__ __forceinline__ uint32_t smem_to_u32(const void* smem_ptr) {
    uint32_t addr;
    asm("{ .reg .u64 tmp; cvta.to.shared.u64 tmp, %1; cvt.u32.u64 %0, tmp; }"
        : "=r"(addr) : "l"(smem_ptr));
    return addr;
}

__device__ __forceinline__ void ldsm_x4(uint32_t& r0, uint32_t& r1, uint32_t& r2, uint32_t& r3,
                                        uint32_t addr) {
    asm volatile("ldmatrix.sync.aligned.m8n8.x4.shared.b16 {%0,%1,%2,%3}, [%4];"
                 : "=r"(r0), "=r"(r1), "=r"(r2), "=r"(r3) : "r"(addr));
}

__device__ __forceinline__ void mma_bf16(float c[4], const unsigned a[4], const unsigned b[2]) {
    asm volatile(
        "mma.sync.aligned.m16n8k16.row.col.f32.bf16.bf16.f32 "
        "{%0,%1,%2,%3},{%4,%5,%6,%7},{%8,%9},{%0,%1,%2,%3};"
        : "+f"(c[0]), "+f"(c[1]), "+f"(c[2]), "+f"(c[3])
        : "r"(a[0]), "r"(a[1]), "r"(a[2]), "r"(a[3]), "r"(b[0]), "r"(b[1]));
}

__device__ __forceinline__ float blockSum256(float v, float* sbuf) {
    #pragma unroll
    for (int o = 16; o; o >>= 1) v += __shfl_xor_sync(0xffffffffu, v, o);
    int w = threadIdx.x >> 5;
    if ((threadIdx.x & 31) == 0) sbuf[w] = v;
    __syncthreads();
    if (threadIdx.x < 32) {
        float s = (threadIdx.x < 8) ? sbuf[threadIdx.x] : 0.f;
        #pragma unroll
        for (int o = 4; o; o >>= 1) s += __shfl_xor_sync(0xffffffffu, s, o);
        if (threadIdx.x == 0) sbuf[0] = s;
    }
    __syncthreads();
    float r = sbuf[0];
    __syncthreads();
    return r;
}

__device__ __forceinline__ const bf16* hbufsel(int id) {
    switch (id) {
        case 0:  return g_Gh;
        case 2:  return g_gPh;
        case 3:  return g_Wfh;
        default: return g_Wbh;
    }
}

// ---------------- small kernels ----------------
__global__ void k_prep(const float* l2, const float* l3, const float* lm,
                       const float* b2p, const float* b3p, const float* bmp,
                       const float* stepp) {
    if (threadIdx.x == 0 && blockIdx.x == 0) {
        const float scale = 0.0625f;
        float lam2 = spf(*l2), lam3 = spf(*l3), lamm = spf(*lm);
        float b2 = fminf(spf(*b2p), 5.f);
        float b3 = fminf(spf(*b3p), 5.f);
        float bm = fminf(spf(*bmp), 5.f);
        g_c.sb2 = b2 * scale;    g_c.sb3 = b3 * scale;    g_c.sbm = bm * scale;
        g_c.cw2 = -lam2 * scale; g_c.cw3 = -lam3 * scale; g_c.cwm = -lamm * scale;
        g_c.ce2 = lam2 / b2;     g_c.ce3 = lam3 / b3;     g_c.cem = lamm / bm;
        g_c.step = (*stepp) * 0.9999f;
        g_EL2 = 0.0; g_EL3 = 0.0; g_ELm = 0.0;
    }
}

// zero CSR counters + tri segment sums (NO gPh zeroing: all slices are now write-once)
__global__ void k_init(int n) {
    int i = blockIdx.x * blockDim.x + threadIdx.x;
    if (i < n) {
        g_cntc[i] = 0;
        g_cntu[i] = 0;
        g_cnt3[i] = 0;
        g_ES3[i] = 0.f;
    }
}

__global__ void k_hist(const int* __restrict__ c2, const int* __restrict__ u2, int ne) {
    int i = blockIdx.x * blockDim.x + threadIdx.x;
    if (i >= ne) return;
    atomicAdd(&g_cntc[c2[i]], 1);
    atomicAdd(&g_cntu[u2[i]], 1);
}

__global__ void k_hist3(const int* __restrict__ c3, const int* __restrict__ u3,
                        const int* __restrict__ v3, int nt) {
    int i = blockIdx.x * blockDim.x + threadIdx.x;
    if (i >= nt) return;
    atomicAdd(&g_cnt3[c3[i]], 1);
    atomicAdd(&g_cnt3[u3[i]], 1);
    atomicAdd(&g_cnt3[v3[i]], 1);
}

__global__ void __launch_bounds__(1024) k_scan(int n) {
    int* cnt = (blockIdx.x == 0) ? g_cntc : ((blockIdx.x == 1) ? g_cntu : g_cnt3);
    int* ofs = (blockIdx.x == 0) ? g_ofsc : ((blockIdx.x == 1) ? g_ofsu : g_ofs3);
    int* pos = (blockIdx.x == 0) ? g_posc : ((blockIdx.x == 1) ? g_posu : g_pos3);
    __shared__ int sp[1024];
    int tid = threadIdx.x;
    int per = (n + 1023) / 1024;
    int b = tid * per;
    int s = 0;
    for (int j = 0; j < per; j++) if (b + j < n) s += cnt[b + j];
    sp[tid] = s;
    __syncthreads();
    int mine = s;
    for (int d = 1; d < 1024; d <<= 1) {
        int v = (tid >= d) ? sp[tid - d] : 0;
        __syncthreads();
        sp[tid] += v;
        __syncthreads();
    }
    int run = sp[tid] - mine;
    for (int j = 0; j < per; j++) {
        if (b + j < n) {
            ofs[b + j] = run;
            pos[b + j] = run;
            run += cnt[b + j];
        }
    }
    if (tid == 1023) ofs[n] = run;
}

__global__ void k_scatter(const int* __restrict__ c2, const int* __restrict__ u2, int ne) {
    int i = blockIdx.x * blockDim.x + threadIdx.x;
    if (i >= ne) return;
    int c = c2[i], u = u2[i];
    int p = atomicAdd(&g_posc[c], 1);
    g_e2c[p] = make_int2(u, i);
    int q = atomicAdd(&g_posu[u], 1);
    g_e2u[q] = make_int2(c, i);
}

__global__ void k_scatter3(const int* __restrict__ c3, const int* __restrict__ u3,
                           const int* __restrict__ v3, const int* __restrict__ t3, int nt) {
    int i = blockIdx.x * blockDim.x + threadIdx.x;
    if (i >= nt) return;
    int c = c3[i], u = u3[i], v = v3[i], tau = t3[i];
    int p;
    p = atomicAdd(&g_pos3[c], 1);
    g_e3[p] = make_int4(u, v, i, tau);          // role 0: gQ3[c] += w*K3[u]*K3[v]*T
    p = atomicAdd(&g_pos3[u], 1);
    g_e3[p] = make_int4(c, v, i, tau | 2);      // role 1: gK3[u] += w*Q3[c]*K3[v]*T
    p = atomicAdd(&g_pos3[v], 1);
    g_e3[p] = make_int4(c, u, i, tau | 2);      // role 1: gK3[v] += w*Q3[c]*K3[u]*T
}

__global__ void k_ln(const float* __restrict__ X, const float* __restrict__ gamma,
                     const float* __restrict__ beta) {
    int row = blockIdx.x, t = threadIdx.x;
    __shared__ float sb[8];
    float x = X[(size_t)row * Dm + t];
    float mu = blockSum256(x, sb) * (1.f / Dm);
    float d = x - mu;
    float var = blockSum256(d * d, sb) * (1.f / Dm);
    float rstd = rsqrtf(var + 1e-5f);
    if (t == 0) { g_mu[row] = mu; g_rstd[row] = rstd; }
    g_Gh[(size_t)row * Dm + t] = __float2bfloat16(d * rstd * gamma[t] + beta[t]);
}

__global__ void k_km(const float* __restrict__ B, const float* __restrict__ W) {
    int k = blockIdx.x, d = threadIdx.x;
    float acc = 0.f;
    for (int i = 0; i < Dm; i++) acc = fmaf(B[k * Dm + i], W[i * Dm + d], acc);
    g_Km[k * Dm + d] = acc;
}

__global__ void k_pack(const float* __restrict__ WQ2, const float* __restrict__ WK2,
                       const float* __restrict__ WQm, const float* __restrict__ WQ3,
                       const float* __restrict__ WK3) {
    int idx = blockIdx.x * blockDim.x + threadIdx.x;
    if (idx >= Dm * PS) return;
    int k = idx / PS, n = idx % PS;
    float w;
    if (n < 256)       w = WQ2[k * 256 + n];
    else if (n < 512)  w = WK2[k * 256 + (n - 256)];
    else if (n < 768)  w = WQm[k * 256 + (n - 512)];
    else if (n < 1280) w = WQ3[k * 512 + (n - 768)];
    else               w = WK3[k * 512 + (n - 1280)];
    bf16 h = __float2bfloat16(w);
    g_Wfh[(size_t)k * PS + n] = h;
    g_Wbh[(size_t)n * Dm + k] = h;
}

// ---------------- GEMM A (R10/R13 config): 128x128 block, 8 warps, 64x32 warp tile ----------------
template <int OUTBF>
__global__ void __launch_bounds__(256) k_gemm(int aid, int bid,
                                              int K, int lda, int ldb, int ldc) {
    const bf16* A = hbufsel(aid);
    const bf16* Bt = hbufsel(bid);
    __shared__ bf16 As[2][128][40];
    __shared__ bf16 Bs[2][128][40];

    const int tid = threadIdx.x;
    const int warp = tid >> 5, lane = tid & 31;
    const int wm = (warp >> 2) << 6;
    const int wn = (warp & 3) << 5;
    const int bm = blockIdx.y << 7, bn = blockIdx.x << 7;
    const int lq = lane >> 2, lr = lane & 3;

    float c[4][4][4];
    #pragma unroll
    for (int i = 0; i < 4; i++)
        #pragma unroll
        for (int j = 0; j < 4; j++)
            #pragma unroll
            for (int e = 0; e < 4; e++) c[i][j][e] = 0.f;

    const int srow = tid >> 1;
    const int sch = (tid & 1) << 1;
    const bf16* aptr = A + (size_t)(bm + srow) * lda + sch * 8;
    const bf16* bptr = Bt + (size_t)(bn + srow) * ldb + sch * 8;

    const uint32_t asbase = smem_to_u32(&As[0][0][0]);
    const uint32_t bsbase = smem_to_u32(&Bs[0][0][0]);

    const int a_row = wm + ((lane >> 3) & 1) * 8 + (lane & 7);
    const int a_kb  = (lane >> 4) * 8;
    const int b_row = wn + (lane >> 4) * 8 + (lane & 7);
    const int b_kb  = ((lane >> 3) & 1) * 8;

    const int KT = K >> 5;
    uint4 ra0, ra1, rb0, rb1;

    ra0 = *(const uint4*)(aptr);
    ra1 = *(const uint4*)(aptr + 8);
    rb0 = *(const uint4*)(bptr);
    rb1 = *(const uint4*)(bptr + 8);
    *(uint4*)(&As[0][srow][sch * 8]) = ra0;
    *(uint4*)(&As[0][srow][sch * 8 + 8]) = ra1;
    *(uint4*)(&Bs[0][srow][sch * 8]) = rb0;
    *(uint4*)(&Bs[0][srow][sch * 8 + 8]) = rb1;
    __syncthreads();

    for (int kt = 0; kt < KT; kt++) {
        const int buf = kt & 1;
        if (kt + 1 < KT) {
            int k0 = (kt + 1) << 5;
            ra0 = *(const uint4*)(aptr + k0);
            ra1 = *(const uint4*)(aptr + k0 + 8);
            rb0 = *(const uint4*)(bptr + k0);
            rb1 = *(const uint4*)(bptr + k0 + 8);
        }
        #pragma unroll
        for (int ks = 0; ks < 2; ks++) {
            unsigned a[4][4], b[4][2];
            #pragma unroll
            for (int mt = 0; mt < 4; mt++) {
                uint32_t addr = asbase +
                    (uint32_t)(((buf * 128 + a_row + mt * 16) * 40 + ks * 16 + a_kb) * 2);
                ldsm_x4(a[mt][0], a[mt][1], a[mt][2], a[mt][3], addr);
            }
            #pragma unroll
            for (int np = 0; np < 2; np++) {
                uint32_t addr = bsbase +
                    (uint32_t)(((buf * 128 + b_row + np * 16) * 40 + ks * 16 + b_kb) * 2);
                ldsm_x4(b[np * 2][0], b[np * 2][1], b[np * 2 + 1][0], b[np * 2 + 1][1], addr);
            }
            #pragma unroll
            for (int mt = 0; mt < 4; mt++)
                #pragma unroll
                for (int nt = 0; nt < 4; nt++) mma_bf16(c[mt][nt], a[mt], b[nt]);
        }
        if (kt + 1 < KT) {
            const int nb = buf ^ 1;
            *(uint4*)(&As[nb][srow][sch * 8]) = ra0;
            *(uint4*)(&As[nb][srow][sch * 8 + 8]) = ra1;
            *(uint4*)(&Bs[nb][srow][sch * 8]) = rb0;
            *(uint4*)(&Bs[nb][srow][sch * 8 + 8]) = rb1;
            __syncthreads();
        }
    }

    #pragma unroll
    for (int mt = 0; mt < 4; mt++) {
        int row = bm + wm + (mt << 4) + lq;
        #pragma unroll
        for (int nt = 0; nt < 4; nt++) {
            int col = bn + wn + (nt << 3) + (lr << 1);
            if (OUTBF) {
                *(unsigned*)(g_Ph + (size_t)row * ldc + col) = f2h(c[mt][nt][0], c[mt][nt][1]);
                *(unsigned*)(g_Ph + (size_t)(row + 8) * ldc + col) = f2h(c[mt][nt][2], c[mt][nt][3]);
            } else {
                *(float2*)(g_gG + (size_t)row * ldc + col) = make_float2(c[mt][nt][0], c[mt][nt][1]);
                *(float2*)(g_gG + (size_t)(row + 8) * ldc + col) = make_float2(c[mt][nt][2], c[mt][nt][3]);
            }
        }
    }
}

// ---------------- GEMM B (R12 config): 128x256 block, 8 warps, 64x64 warp tile ----------------
#define G2_SMEM 61440

template <int OUTBF>
__global__ void __launch_bounds__(256) k_gemm2(int aid, int bid,
                                               int K, int lda, int ldb, int ldc) {
    extern __shared__ __align__(16) bf16 smd[];
    bf16* As = smd;                 // [2][128][40]
    bf16* Bs = smd + 2 * 128 * 40;  // [2][256][40]
    const bf16* A = hbufsel(aid);
    const bf16* Bt = hbufsel(bid);

    const int tid = threadIdx.x;
    const int warp = tid >> 5, lane = tid & 31;
    const int wm = (warp >> 2) << 6;
    const int wn = (warp & 3) << 6;
    const int bm = blockIdx.y << 7, bn = blockIdx.x << 8;
    const int lq = lane >> 2, lr = lane & 3;

    float c[4][8][4];
    #pragma unroll
    for (int i = 0; i < 4; i++)
        #pragma unroll
        for (int j = 0; j < 8; j++)
            #pragma unroll
            for (int e = 0; e < 4; e++) c[i][j][e] = 0.f;

    const int sarow = tid >> 1;
    const int sach = (tid & 1) << 1;
    const bf16* aptr = A + (size_t)(bm + sarow) * lda + sach * 8;
    const bf16* bptr = Bt + (size_t)(bn + tid) * ldb;

    const uint32_t asbase = smem_to_u32(As);
    const uint32_t bsbase = smem_to_u32(Bs);

    const int a_row = wm + ((lane >> 3) & 1) * 8 + (lane & 7);
    const int a_kb  = (lane >> 4) * 8;
    const int b_row = wn + (lane >> 4) * 8 + (lane & 7);
    const int b_kb  = ((lane >> 3) & 1) * 8;

    const int KT = K >> 5;
    uint4 pa0, pa1, pb0, pb1, pb2, pb3;

    pa0 = *(const uint4*)(aptr);
    pa1 = *(const uint4*)(aptr + 8);
    pb0 = *(const uint4*)(bptr);
    pb1 = *(const uint4*)(bptr + 8);
    pb2 = *(const uint4*)(bptr + 16);
    pb3 = *(const uint4*)(bptr + 24);
    *(uint4*)(As + sarow * 40 + sach * 8) = pa0;
    *(uint4*)(As + sarow * 40 + sach * 8 + 8) = pa1;
    *(uint4*)(Bs + tid * 40 + 0) = pb0;
    *(uint4*)(Bs + tid * 40 + 8) = pb1;
    *(uint4*)(Bs + tid * 40 + 16) = pb2;
    *(uint4*)(Bs + tid * 40 + 24) = pb3;
    __syncthreads();

    for (int kt = 0; kt < KT; kt++) {
        const int buf = kt & 1;
        if (kt + 1 < KT) {
            int k0 = (kt + 1) << 5;
            pa0 = *(const uint4*)(aptr + k0);
            pa1 = *(const uint4*)(aptr + k0 + 8);
            pb0 = *(const uint4*)(bptr + k0);
            pb1 = *(const uint4*)(bptr + k0 + 8);
            pb2 = *(const uint4*)(bptr + k0 + 16);
            pb3 = *(const uint4*)(bptr + k0 + 24);
        }
        #pragma unroll
        for (int ks = 0; ks < 2; ks++) {
            unsigned a[4][4], b[8][2];
            #pragma unroll
            for (int mt = 0; mt < 4; mt++) {
                uint32_t addr = asbase +
                    (uint32_t)(((buf * 128 + a_row + mt * 16) * 40 + ks * 16 + a_kb) * 2);
                ldsm_x4(a[mt][0], a[mt][1], a[mt][2], a[mt][3], addr);
            }
            #pragma unroll
            for (int np = 0; np < 4; np++) {
                uint32_t addr = bsbase +
                    (uint32_t)(((buf * 256 + b_row + np * 16) * 40 + ks * 16 + b_kb) * 2);
                ldsm_x4(b[np * 2][0], b[np * 2][1], b[np * 2 + 1][0], b[np * 2 + 1][1], addr);
            }
            #pragma unroll
            for (int mt = 0; mt < 4; mt++)
                #pragma unroll
                for (int nt = 0; nt < 8; nt++) mma_bf16(c[mt][nt], a[mt], b[nt]);
        }
        if (kt + 1 < KT) {
            const int nb = buf ^ 1;
            *(uint4*)(As + (nb * 128 + sarow) * 40 + sach * 8) = pa0;
            *(uint4*)(As + (nb * 128 + sarow) * 40 + sach * 8 + 8) = pa1;
            *(uint4*)(Bs + (nb * 256 + tid) * 40 + 0) = pb0;
            *(uint4*)(Bs + (nb * 256 + tid) * 40 + 8) = pb1;
            *(uint4*)(Bs + (nb * 256 + tid) * 40 + 16) = pb2;
            *(uint4*)(Bs + (nb * 256 + tid) * 40 + 24) = pb3;
            __syncthreads();
        }
    }

    #pragma unroll
    for (int mt = 0; mt < 4; mt++) {
        int row = bm + wm + (mt << 4) + lq;
        #pragma unroll
        for (int nt = 0; nt < 8; nt++) {
            int col = bn + wn + (nt << 3) + (lr << 1);
            if (OUTBF) {
                *(unsigned*)(g_Ph + (size_t)row * ldc + col) = f2h(c[mt][nt][0], c[mt][nt][1]);
                *(unsigned*)(g_Ph + (size_t)(row + 8) * ldc + col) = f2h(c[mt][nt][2], c[mt][nt][3]);
            } else {
                *(float2*)(g_gG + (size_t)row * ldc + col) = make_float2(c[mt][nt][0], c[mt][nt][1]);
                *(float2*)(g_gG + (size_t)(row + 8) * ldc + col) = make_float2(c[mt][nt][2], c[mt][nt][3]);
            }
        }
    }
}

// ---------------- edge passes: depth-2 software pipeline (R13) ----------------
__global__ void __launch_bounds__(256) k_edgeA(int n) {
    int wid = threadIdx.x >> 5, lane = threadIdx.x & 31;
    int c = blockIdx.x * 8 + wid;
    float lse = 0.f;
    if (c < n) {
        int beg = g_ofsc[c], end = g_ofsc[c + 1];
        float qf[8];
        unpack8(*(const uint4*)(g_Ph + (size_t)c * PS + OQ2 + lane * 8), qf);
        float se = 0.f;
        float acc[8];
        #pragma unroll
        for (int j = 0; j < 8; j++) acc[j] = 0.f;
        float sb2 = g_c.sb2;

        int2 pr0, pr1; uint4 kv0;
        if (beg < end) {
            pr0 = g_e2c[beg];
            if (beg + 1 < end) pr1 = g_e2c[beg + 1];
            kv0 = *(const uint4*)(g_Ph + (size_t)pr0.x * PS + OK2 + lane * 8);
        }
        for (int e = beg; e < end; e++) {
            int2 prn; uint4 kvn;
            if (e + 2 < end) prn = g_e2c[e + 2];
            if (e + 1 < end) kvn = *(const uint4*)(g_Ph + (size_t)pr1.x * PS + OK2 + lane * 8);
            float kf[8];
            unpack8(kv0, kf);
            float s = qf[0]*kf[0] + qf[1]*kf[1] + qf[2]*kf[2] + qf[3]*kf[3]
                    + qf[4]*kf[4] + qf[5]*kf[5] + qf[6]*kf[6] + qf[7]*kf[7];
            #pragma unroll
            for (int o = 16; o; o >>= 1) s += __shfl_xor_sync(0xffffffffu, s, o);
            float es = expf(s * sb2);
            if (!lane) g_S2[pr0.y] = es;
            se += es;
            #pragma unroll
            for (int j = 0; j < 8; j++) acc[j] = fmaf(es, kf[j], acc[j]);
            pr0 = pr1; pr1 = prn; kv0 = kvn;
        }
        uint4 o = make_uint4(0, 0, 0, 0);
        float invw = 0.f;
        if (end > beg) {
            lse = logf(se);
            invw = g_c.cw2 / se;
            o.x = f2h(acc[0] * invw, acc[1] * invw);
            o.y = f2h(acc[2] * invw, acc[3] * invw);
            o.z = f2h(acc[4] * invw, acc[5] * invw);
            o.w = f2h(acc[6] * invw, acc[7] * invw);
        }
        *(uint4*)(g_gPh + (size_t)c * PS + OQ2 + lane * 8) = o;
        if (!lane) g_LSE2[c] = invw;
    }
    __shared__ float sl[8];
    if (!lane) sl[wid] = (c < n) ? lse : 0.f;
    __syncthreads();
    if (threadIdx.x == 0) {
        float t = 0.f;
        #pragma unroll
        for (int i = 0; i < 8; i++) t += sl[i];
        atomicAdd(&g_EL2, (double)t);
    }
}

__global__ void __launch_bounds__(256) k_edgeB(int n) {
    int wid = threadIdx.x >> 5, lane = threadIdx.x & 31;
    int u = blockIdx.x * 8 + wid;
    if (u >= n) return;
    int beg = g_ofsu[u], end = g_ofsu[u + 1];
    float acc[8];
    #pragma unroll
    for (int j = 0; j < 8; j++) acc[j] = 0.f;

    int2 pr0, pr1; uint4 qv0; float w0 = 0.f;
    if (beg < end) {
        pr0 = g_e2u[beg];
        if (beg + 1 < end) pr1 = g_e2u[beg + 1];
        qv0 = *(const uint4*)(g_Ph + (size_t)pr0.x * PS + OQ2 + lane * 8);
        w0 = g_S2[pr0.y] * g_LSE2[pr0.x];
    }
    for (int e = beg; e < end; e++) {
        int2 prn; uint4 qvn; float wn = 0.f;
        if (e + 2 < end) prn = g_e2u[e + 2];
        if (e + 1 < end) {
            qvn = *(const uint4*)(g_Ph + (size_t)pr1.x * PS + OQ2 + lane * 8);
            wn = g_S2[pr1.y] * g_LSE2[pr1.x];
        }
        float qf[8];
        unpack8(qv0, qf);
        #pragma unroll
        for (int j = 0; j < 8; j++) acc[j] = fmaf(w0, qf[j], acc[j]);
        pr0 = pr1; pr1 = prn; qv0 = qvn; w0 = wn;
    }
    uint4 o;
    o.x = f2h(acc[0], acc[1]);
    o.y = f2h(acc[2], acc[3]);
    o.z = f2h(acc[4], acc[5]);
    o.w = f2h(acc[6], acc[7]);
    *(uint4*)(g_gPh + (size_t)u * PS + OK2 + lane * 8) = o;
}

// triangle score: es = exp(s), fused segment-sum via atomicAdd
__global__ void k_tri_dot(const int* __restrict__ ci, const int* __restrict__ ui,
                          const int* __restrict__ vi, const int* __restrict__ ti,
                          const float* __restrict__ T, int nt) {
    int gw = (blockIdx.x * blockDim.x + threadIdx.x) >> 5;
    int lane = threadIdx.x & 31;
    if (gw >= nt) return;
    int c = ci[gw], u = ui[gw], v = vi[gw], tau = ti[gw];
    const uint4* q  = (const uint4*)(g_Ph + (size_t)c * PS + OQ3);
    const uint4* ku = (const uint4*)(g_Ph + (size_t)u * PS + OK3);
    const uint4* kv = (const uint4*)(g_Ph + (size_t)v * PS + OK3);
    const float4* tp = (const float4*)(T + (size_t)tau * RDm);
    float s = 0.f;
    #pragma unroll
    for (int f = 0; f < 2; f++) {
        int idx = lane + f * 32;
        float a[8], b[8], cc[8];
        unpack8(q[idx], a); unpack8(ku[idx], b); unpack8(kv[idx], cc);
        float4 t0 = tp[idx * 2], t1 = tp[idx * 2 + 1];
        s += a[0]*b[0]*cc[0]*t0.x + a[1]*b[1]*cc[1]*t0.y
           + a[2]*b[2]*cc[2]*t0.z + a[3]*b[3]*cc[3]*t0.w
           + a[4]*b[4]*cc[4]*t1.x + a[5]*b[5]*cc[5]*t1.y
           + a[6]*b[6]*cc[6]*t1.z + a[7]*b[7]*cc[7]*t1.w;
    }
    #pragma unroll
    for (int o = 16; o; o >>= 1) s += __shfl_xor_sync(0xffffffffu, s, o);
    if (!lane) {
        float es = expf(s * g_c.sb3);
        g_S3[gw] = es;
        atomicAdd(&g_ES3[c], es);
    }
}

__global__ void k_seglse3(int n) {
    int i = blockIdx.x * blockDim.x + threadIdx.x;
    __shared__ float sb[8];
    float lse = 0.f;
    if (i < n) {
        float es = g_ES3[i];
        float inv = 0.f;
        if (es > 0.f) { lse = logf(es); inv = 1.f / es; }
        g_LSE3[i] = inv;
    }
    float tot = blockSum256(lse, sb);
    if (threadIdx.x == 0) atomicAdd(&g_EL3, (double)tot);
}

// triangle gradients via node CSR: warp per node, register accumulation,
// single write of gQ3 and gK3 slices (no atomics, no pre-zeroing needed).
__global__ void __launch_bounds__(256) k_triN(const float* __restrict__ T, int n) {
    int wid = threadIdx.x >> 5, lane = threadIdx.x & 31;
    int node = blockIdx.x * 8 + wid;
    if (node >= n) return;
    int beg = g_ofs3[node], end = g_ofs3[node + 1];
    float accQ[16], accK[16];
    #pragma unroll
    for (int j = 0; j < 16; j++) { accQ[j] = 0.f; accK[j] = 0.f; }
    float cw3 = g_c.cw3;

    for (int e = beg; e < end; e++) {
        int4 en = g_e3[e];
        int a = en.x, b = en.y, tri = en.z;
        int tau = en.w & 1, role = en.w >> 1;
        // role 0: node is c -> opA=K3[a], opB=K3[b], out gQ3, lse node
        // role 1: node is u/v -> opA=Q3[a], opB=K3[b], out gK3, lse a
        float w = cw3 * g_S3[tri] * g_LSE3[role ? a : node];
        const uint4* pa = (const uint4*)(g_Ph + (size_t)a * PS + (role ? OQ3 : OK3) + lane * 16);
        const uint4* pb = (const uint4*)(g_Ph + (size_t)b * PS + OK3 + lane * 16);
        float fa[16], fb[16];
        unpack8(pa[0], fa); unpack8(pa[1], fa + 8);
        unpack8(pb[0], fb); unpack8(pb[1], fb + 8);
        const float4* tp = (const float4*)(T + (size_t)tau * RDm + lane * 16);
        float4 t0 = tp[0], t1 = tp[1], t2 = tp[2], t3 = tp[3];
        float tf[16];
        tf[0]=t0.x; tf[1]=t0.y; tf[2]=t0.z; tf[3]=t0.w;
        tf[4]=t1.x; tf[5]=t1.y; tf[6]=t1.z; tf[7]=t1.w;
        tf[8]=t2.x; tf[9]=t2.y; tf[10]=t2.z; tf[11]=t2.w;
        tf[12]=t3.x; tf[13]=t3.y; tf[14]=t3.z; tf[15]=t3.w;
        if (role) {
            #pragma unroll
            for (int j = 0; j < 16; j++) accK[j] = fmaf(w * tf[j], fa[j] * fb[j], accK[j]);
        } else {
            #pragma unroll
            for (int j = 0; j < 16; j++) accQ[j] = fmaf(w * tf[j], fa[j] * fb[j], accQ[j]);
        }
    }
    // write both slices (write-once; covers empty nodes with zeros)
    uint4 oq0, oq1, ok0, ok1;
    oq0.x = f2h(accQ[0], accQ[1]);  oq0.y = f2h(accQ[2], accQ[3]);
    oq0.z = f2h(accQ[4], accQ[5]);  oq0.w = f2h(accQ[6], accQ[7]);
    oq1.x = f2h(accQ[8], accQ[9]);  oq1.y = f2h(accQ[10], accQ[11]);
    oq1.z = f2h(accQ[12], accQ[13]); oq1.w = f2h(accQ[14], accQ[15]);
    ok0.x = f2h(accK[0], accK[1]);  ok0.y = f2h(accK[2], accK[3]);
    ok0.z = f2h(accK[4], accK[5]);  ok0.w = f2h(accK[6], accK[7]);
    ok1.x = f2h(accK[8], accK[9]);  ok1.y = f2h(accK[10], accK[11]);
    ok1.z = f2h(accK[12], accK[13]); ok1.w = f2h(accK[14], accK[15]);
    uint4* dq = (uint4*)(g_gPh + (size_t)node * PS + OQ3 + lane * 16);
    dq[0] = oq0;
    dq[1] = oq1;
    uint4* dk = (uint4*)(g_gPh + (size_t)node * PS + OK3 + lane * 16);
    dk[0] = ok0;
    dk[1] = ok1;
}

__global__ void __launch_bounds__(256) k_mem(int n) {
    __shared__ float sKm[KSLOT * Dm];
    for (int i = threadIdx.x; i < KSLOT * Dm; i += 256) sKm[i] = g_Km[i];
    __syncthreads();
    int wid = threadIdx.x >> 5, lane = threadIdx.x & 31;
    int row = blockIdx.x * 8 + wid;
    if (row >= n) return;
    float qf[8];
    unpack8(*(const uint4*)(g_Ph + (size_t)row * PS + OQm + lane * 8), qf);
    float myS = 0.f;
    float sbm = g_c.sbm;
    #pragma unroll
    for (int k0 = 0; k0 < KSLOT; k0 += 4) {
        float d[4];
        #pragma unroll
        for (int j = 0; j < 4; j++) {
            const float4* kp = (const float4*)(sKm + (k0 + j) * Dm + lane * 8);
            float4 a = kp[0], b = kp[1];
            d[j] = qf[0]*a.x + qf[1]*a.y + qf[2]*a.z + qf[3]*a.w
                 + qf[4]*b.x + qf[5]*b.y + qf[6]*b.z + qf[7]*b.w;
        }
        #pragma unroll
        for (int o = 16; o; o >>= 1) {
            #pragma unroll
            for (int j = 0; j < 4; j++) d[j] += __shfl_xor_sync(0xffffffffu, d[j], o);
        }
        #pragma unroll
        for (int j = 0; j < 4; j++)
            if (lane == k0 + j) myS = sbm * d[j];
    }
    float m = myS;
    #pragma unroll
    for (int o = 16; o; o >>= 1) m = fmaxf(m, __shfl_xor_sync(0xffffffffu, m, o));
    float e = expf(myS - m);
    #pragma unroll
    for (int o = 16; o; o >>= 1) e += __shfl_xor_sync(0xffffffffu, e, o);
    float lse = m + logf(e);
    float p = expf(myS - lse);
    float acc[8];
    #pragma unroll
    for (int j = 0; j < 8; j++) acc[j] = 0.f;
    #pragma unroll 4
    for (int k = 0; k < KSLOT; k++) {
        float pk = __shfl_sync(0xffffffffu, p, k);
        const float4* kp = (const float4*)(sKm + k * Dm + lane * 8);
        float4 k0 = kp[0], k1 = kp[1];
        acc[0] = fmaf(pk, k0.x, acc[0]); acc[1] = fmaf(pk, k0.y, acc[1]);
        acc[2] = fmaf(pk, k0.z, acc[2]); acc[3] = fmaf(pk, k0.w, acc[3]);
        acc[4] = fmaf(pk, k1.x, acc[4]); acc[5] = fmaf(pk, k1.y, acc[5]);
        acc[6] = fmaf(pk, k1.z, acc[6]); acc[7] = fmaf(pk, k1.w, acc[7]);
    }
    float cw = g_c.cwm;
    uint4 outv;
    outv.x = f2h(cw * acc[0], cw * acc[1]);
    outv.y = f2h(cw * acc[2], cw * acc[3]);
    outv.z = f2h(cw * acc[4], cw * acc[5]);
    outv.w = f2h(cw * acc[6], cw * acc[7]);
    *(uint4*)(g_gPh + (size_t)row * PS + OQm + lane * 8) = outv;
    __shared__ float sl[8];
    if (!lane) sl[wid] = lse;
    __syncthreads();
    if (threadIdx.x == 0) {
        float t = 0.f;
        #pragma unroll
        for (int i = 0; i < 8; i++) t += sl[i];
        atomicAdd(&g_ELm, (double)t);
    }
}

__global__ void k_final(const float* __restrict__ X, const float* __restrict__ gamma,
                        float* __restrict__ out, int n, int out_size) {
    int row = blockIdx.x, t = threadIdx.x;
    __shared__ float sb[8];
    float rstd = g_rstd[row], mu = g_mu[row];
    float x = X[(size_t)row * Dm + t];
    float xh = (x - mu) * rstd;
    float gh = g_gG[(size_t)row * Dm + t] * gamma[t];
    float s1 = blockSum256(gh, sb) * (1.f / Dm);
    float s2 = blockSum256(gh * xh, sb) * (1.f / Dm);
    float gx = rstd * (gh - s1 - xh * s2);
    float gn2 = blockSum256(gx * gx, sb);
    float gn = fmaxf(sqrtf(gn2), 1e-6f);
    float fg = fminf(1.0f / gn, 1.0f);
    float xn = x - g_c.step * fg * gx;
    float sn2 = blockSum256(xn * xn, sb);
    float sn = fmaxf(sqrtf(sn2), 1e-6f);
    float fs = fminf(10.0f / sn, 1.0f);
    out[(size_t)row * Dm + t] = xn * fs;
    if (row == 0 && t == 0 && out_size > n * Dm) {
        double E = -((double)g_c.ce2 * g_EL2 + (double)g_c.ce3 * g_EL3 + (double)g_c.cem * g_ELm);
        out[(size_t)n * Dm] = (float)E;
    }
}

// ---------------- launch ----------------
extern "C" void kernel_launch(void* const* d_in, const int* in_sizes, int n_in,
                              void* d_out, int out_size) {
    const float* X     = (const float*)d_in[0];
    const int* c2      = (const int*)d_in[1];
    const int* u2      = (const int*)d_in[2];
    const int* c3      = (const int*)d_in[3];
    const int* u3      = (const int*)d_in[4];
    const int* v3      = (const int*)d_in[5];
    const int* ttau    = (const int*)d_in[6];
    const float* stepp = (const float*)d_in[7];
    const float* gamma = (const float*)d_in[8];
    const float* beta  = (const float*)d_in[9];
    const float* WQ2   = (const float*)d_in[10];
    const float* WK2   = (const float*)d_in[11];
    const float* WQ3   = (const float*)d_in[12];
    const float* WK3   = (const float*)d_in[13];
    const float* Ttau  = (const float*)d_in[14];
    const float* WQm   = (const float*)d_in[15];
    const float* WKm   = (const float*)d_in[16];
    const float* Bmem  = (const float*)d_in[17];
    const float* l2    = (const float*)d_in[18];
    const float* l3    = (const float*)d_in[19];
    const float* lm    = (const float*)d_in[20];
    const float* b2    = (const float*)d_in[21];
    const float* b3    = (const float*)d_in[22];
    const float* bm    = (const float*)d_in[23];
    float* out = (float*)d_out;

    int N  = in_sizes[0] / Dm;
    int ne = in_sizes[1];
    int nt = in_sizes[3];
    if (N > NMAX) N = NMAX;
    if (ne > NEMAX) ne = NEMAX;
    if (nt > NTMAX) nt = NTMAX;

    cudaFuncSetAttribute(k_gemm2<0>, cudaFuncAttributeMaxDynamicSharedMemorySize, G2_SMEM);

    // launches 1-3: prerequisites for the forward GEMM
    k_prep<<<1, 32>>>(l2, l3, lm, b2, b3, bm, stepp);
    k_ln<<<N, 256>>>(X, gamma, beta);
    k_pack<<<(Dm * PS + 255) / 256, 256>>>(WQ2, WK2, WQm, WQ3, WK3);

    // launch 4 (ncu-profiled slot): fused forward projection P = G @ Wf (R13 tile)
    k_gemm<1><<<dim3(PS / 128, N / 128), 256>>>(0, 4, Dm, Dm, Dm, PS);

    // CSR build + remaining setup (no gPh zeroing anymore)
    k_init<<<(N + 255) / 256, 256>>>(N);
    k_hist<<<(ne + 255) / 256, 256>>>(c2, u2, ne);
    k_hist3<<<(nt + 255) / 256, 256>>>(c3, u3, v3, nt);
    k_km<<<KSLOT, Dm>>>(Bmem, WKm);
    k_scan<<<3, 1024>>>(N);
    k_scatter<<<(ne + 255) / 256, 256>>>(c2, u2, ne);
    k_scatter3<<<(nt + 255) / 256, 256>>>(c3, u3, v3, ttau, nt);

    // edge (order-2): pipelined CSR node passes
    int nbl = (N + 7) / 8;
    k_edgeA<<<nbl, 256>>>(N);
    k_edgeB<<<nbl, 256>>>(N);

    // triangle (order-3): scores + segment sums, then CSR gradient pass
    int tbl = (nt + 7) / 8;
    k_tri_dot<<<tbl, 256>>>(c3, u3, v3, ttau, Ttau, nt);
    k_seglse3<<<(N + 255) / 256, 256>>>(N);
    k_triN<<<nbl, 256>>>(Ttau, N);

    // memory-slot energy + gQm
    k_mem<<<N / 8, 256>>>(N);

    // fused backward projection: gG = gP @ Wf^T (K=1792), 256-wide N tile
    k_gemm2<0><<<dim3(Dm / 256, N / 128), 256, G2_SMEM>>>(2, 3, PS, PS, PS, Dm);

    k_final<<<N, 256>>>(X, gamma, out, N, out_size);
}

// round 16
// speedup vs baseline: 1.0845x; 1.0845x over previous
#include <cuda_runtime.h>
#include <cuda_bf16.h>
#include <cstdint>
#include <math.h>

#define Dm    256
#define NMAX  32768
#define NEMAX 1000000
#define NTMAX 65536
#define KSLOT 32
#define RDm   512
#define PS    1792   // packed row stride: Q2|K2|Qm|Q3|K3
#define OQ2   0
#define OK2   256
#define OQm   512
#define OQ3   768
#define OK3   1280

typedef __nv_bfloat16 bf16;
typedef __nv_bfloat162 bf162;

// ---------------- static device scratch ----------------
__device__ __align__(16) bf16  g_Gh[(size_t)NMAX * Dm];
__device__ __align__(16) bf16  g_Ph[(size_t)NMAX * PS];
__device__ __align__(16) bf16  g_gPh[(size_t)NMAX * PS];
__device__ __align__(16) bf16  g_Wfh[(size_t)Dm * PS];
__device__ __align__(16) bf16  g_Wbh[(size_t)PS * Dm];
__device__ __align__(16) float g_gG[(size_t)NMAX * Dm];
__device__ float g_mu[NMAX];
__device__ float g_rstd[NMAX];
__device__ float g_Km[KSLOT * Dm];
__device__ float g_S2[NEMAX];   // exp(s2)
__device__ float g_S3[NTMAX];   // exp(s3)
__device__ float g_ES3[NMAX];   // sum exp(s3) per segment
__device__ float g_LSE2[NMAX];  // cw2 / sum(exp(s2))
__device__ double g_EL2, g_EL3, g_ELm;
// CSR for edges
__device__ int  g_cntc[NMAX], g_cntu[NMAX];
__device__ int  g_ofsc[NMAX + 1], g_ofsu[NMAX + 1];
__device__ int  g_posc[NMAX], g_posu[NMAX];
__device__ int2 g_e2c[NEMAX];
__device__ int2 g_e2u[NEMAX];

struct Consts {
    float sb2, sb3, sbm;
    float cw2, cw3, cwm;
    float ce2, ce3, cem;
    float step;
};
__device__ Consts g_c;

// ---------------- generic helpers ----------------
__device__ __forceinline__ float spf(float x) { return x > 20.f ? x : log1pf(expf(x)); }

__device__ __forceinline__ float2 h2f(unsigned u) {
    bf162 h = *(bf162*)&u;
    return __bfloat1622float2(h);
}
__device__ __forceinline__ unsigned f2h(float a, float b) {
    bf162 h = __floats2bfloat162_rn(a, b);
    return *(unsigned*)&h;
}
__device__ __forceinline__ void unpack8(uint4 v, float* f) {
    float2 p;
    p = h2f(v.x); f[0] = p.x; f[1] = p.y;
    p = h2f(v.y); f[2] = p.x; f[3] = p.y;
    p = h2f(v.z); f[4] = p.x; f[5] = p.y;
    p = h2f(v.w); f[6] = p.x; f[7] = p.y;
}

__device__ __forceinline__ void red16h(bf16* p, unsigned r0, unsigned r1, unsigned r2, unsigned r3) {
    asm volatile("red.global.add.noftz.v4.bf16x2 [%0], {%1,%2,%3,%4};"
                 :: "l"(__cvta_generic_to_global(p)), "r"(r0), "r"(r1), "r"(r2), "r"(r3)
                 : "memory");
}

__device__ __forceinline__ uint32_t smem_to_u32(const void* smem_ptr) {
    uint32_t addr;
    asm("{ .reg .u64 tmp; cvta.to.shared.u64 tmp, %1; cvt.u32.u64 %0, tmp; }"
        : "=r"(addr) : "l"(smem_ptr));
    return addr;
}

__device__ __forceinline__ void ldsm_x4(uint32_t& r0, uint32_t& r1, uint32_t& r2, uint32_t& r3,
                                        uint32_t addr) {
    asm volatile("ldmatrix.sync.aligned.m8n8.x4.shared.b16 {%0,%1,%2,%3}, [%4];"
                 : "=r"(r0), "=r"(r1), "=r"(r2), "=r"(r3) : "r"(addr));
}

__device__ __forceinline__ void mma_bf16(float c[4], const unsigned a[4], const unsigned b[2]) {
    asm volatile(
        "mma.sync.aligned.m16n8k16.row.col.f32.bf16.bf16.f32 "
        "{%0,%1,%2,%3},{%4,%5,%6,%7},{%8,%9},{%0,%1,%2,%3};"
        : "+f"(c[0]), "+f"(c[1]), "+f"(c[2]), "+f"(c[3])
        : "r"(a[0]), "r"(a[1]), "r"(a[2]), "r"(a[3]), "r"(b[0]), "r"(b[1]));
}

__device__ __forceinline__ float blockSum256(float v, float* sbuf) {
    #pragma unroll
    for (int o = 16; o; o >>= 1) v += __shfl_xor_sync(0xffffffffu, v, o);
    int w = threadIdx.x >> 5;
    if ((threadIdx.x & 31) == 0) sbuf[w] = v;
    __syncthreads();
    if (threadIdx.x < 32) {
        float s = (threadIdx.x < 8) ? sbuf[threadIdx.x] : 0.f;
        #pragma unroll
        for (int o = 4; o; o >>= 1) s += __shfl_xor_sync(0xffffffffu, s, o);
        if (threadIdx.x == 0) sbuf[0] = s;
    }
    __syncthreads();
    float r = sbuf[0];
    __syncthreads();
    return r;
}

__device__ __forceinline__ const bf16* hbufsel(int id) {
    switch (id) {
        case 0:  return g_Gh;
        case 2:  return g_gPh;
        case 3:  return g_Wfh;
        default: return g_Wbh;
    }
}

// ================= fused setup kernel (kA) =================
// sections: [0,N) ln | [N,N+1792) pack | +32 km | +2048 init(+prep in block 0)
__global__ void __launch_bounds__(256) kA(const float* __restrict__ X,
                                          const float* __restrict__ gamma,
                                          const float* __restrict__ beta,
                                          const float* __restrict__ WQ2,
                                          const float* __restrict__ WK2,
                                          const float* __restrict__ WQm,
                                          const float* __restrict__ WQ3,
                                          const float* __restrict__ WK3,
                                          const float* __restrict__ Bmem,
                                          const float* __restrict__ WKm,
                                          const float* l2, const float* l3, const float* lm,
                                          const float* b2p, const float* b3p, const float* bmp,
                                          const float* stepp, int n) {
    __shared__ float sb[8];
    int bid = blockIdx.x, t = threadIdx.x;
    if (bid < n) {
        // ---- layernorm ----
        int row = bid;
        float x = X[(size_t)row * Dm + t];
        float mu = blockSum256(x, sb) * (1.f / Dm);
        float d = x - mu;
        float var = blockSum256(d * d, sb) * (1.f / Dm);
        float rstd = rsqrtf(var + 1e-5f);
        if (t == 0) { g_mu[row] = mu; g_rstd[row] = rstd; }
        g_Gh[(size_t)row * Dm + t] = __float2bfloat16(d * rstd * gamma[t] + beta[t]);
        return;
    }
    bid -= n;
    if (bid < 1792) {
        // ---- weight pack: 256 elements of 7 rows each handled per block ----
        for (int r = 0; r < 1; r++) {}  // (keep structure simple)
        int idx0 = bid * 256 + t;       // covers 1792*256 = 458752 = Dm*PS
        int k = idx0 / PS, nn = idx0 % PS;
        float w;
        if (nn < 256)       w = WQ2[k * 256 + nn];
        else if (nn < 512)  w = WK2[k * 256 + (nn - 256)];
        else if (nn < 768)  w = WQm[k * 256 + (nn - 512)];
        else if (nn < 1280) w = WQ3[k * 512 + (nn - 768)];
        else                w = WK3[k * 512 + (nn - 1280)];
        bf16 h = __float2bfloat16(w);
        g_Wfh[(size_t)k * PS + nn] = h;
        g_Wbh[(size_t)nn * Dm + k] = h;
        return;
    }
    bid -= 1792;
    if (bid < 32) {
        // ---- Km = Bmem @ WKm ----
        int k = bid, dcol = t;
        float acc = 0.f;
        for (int i = 0; i < Dm; i++) acc = fmaf(Bmem[k * Dm + i], WKm[i * Dm + dcol], acc);
        g_Km[k * Dm + dcol] = acc;
        return;
    }
    bid -= 32;
    // ---- init section (2048 blocks): prep + counters + gPh tri-region zero ----
    if (bid == 0 && t == 0) {
        const float scale = 0.0625f;
        float lam2 = spf(*l2), lam3 = spf(*l3), lamm = spf(*lm);
        float b2 = fminf(spf(*b2p), 5.f);
        float b3 = fminf(spf(*b3p), 5.f);
        float bm = fminf(spf(*bmp), 5.f);
        g_c.sb2 = b2 * scale;    g_c.sb3 = b3 * scale;    g_c.sbm = bm * scale;
        g_c.cw2 = -lam2 * scale; g_c.cw3 = -lam3 * scale; g_c.cwm = -lamm * scale;
        g_c.ce2 = lam2 / b2;     g_c.ce3 = lam3 / b3;     g_c.cem = lamm / bm;
        g_c.step = (*stepp) * 0.9999f;
        g_EL2 = 0.0; g_EL3 = 0.0; g_ELm = 0.0;
    }
    size_t stride = (size_t)2048 * 256;
    size_t i0 = (size_t)bid * 256 + t;
    for (size_t i = i0; i < (size_t)n; i += stride) {
        g_cntc[i] = 0; g_cntu[i] = 0; g_ES3[i] = 0.f;
    }
    uint4 z = make_uint4(0, 0, 0, 0);
    size_t tot = (size_t)n * 128;   // zero gPh cols [OQ3, PS): 128 uint4/row
    for (size_t i = i0; i < tot; i += stride) {
        size_t row = i >> 7;
        size_t ch = i & 127;
        *(uint4*)(g_gPh + row * PS + OQ3 + ch * 8) = z;
    }
}

// ---------------- CSR build ----------------
__global__ void k_hist(const int* __restrict__ c2, const int* __restrict__ u2, int ne) {
    int i = blockIdx.x * blockDim.x + threadIdx.x;
    if (i >= ne) return;
    atomicAdd(&g_cntc[c2[i]], 1);
    atomicAdd(&g_cntu[u2[i]], 1);
}

__global__ void __launch_bounds__(1024) k_scan(int n) {
    int* cnt = blockIdx.x ? g_cntu : g_cntc;
    int* ofs = blockIdx.x ? g_ofsu : g_ofsc;
    int* pos = blockIdx.x ? g_posu : g_posc;
    __shared__ int sp[1024];
    int tid = threadIdx.x;
    int per = (n + 1023) / 1024;
    int b = tid * per;
    int s = 0;
    for (int j = 0; j < per; j++) if (b + j < n) s += cnt[b + j];
    sp[tid] = s;
    __syncthreads();
    int mine = s;
    for (int d = 1; d < 1024; d <<= 1) {
        int v = (tid >= d) ? sp[tid - d] : 0;
        __syncthreads();
        sp[tid] += v;
        __syncthreads();
    }
    int run = sp[tid] - mine;
    for (int j = 0; j < per; j++) {
        if (b + j < n) {
            ofs[b + j] = run;
            pos[b + j] = run;
            run += cnt[b + j];
        }
    }
    if (tid == 1023) ofs[n] = run;
}

__global__ void k_scatter(const int* __restrict__ c2, const int* __restrict__ u2, int ne) {
    int i = blockIdx.x * blockDim.x + threadIdx.x;
    if (i >= ne) return;
    int c = c2[i], u = u2[i];
    int p = atomicAdd(&g_posc[c], 1);
    g_e2c[p] = make_int2(u, i);
    int q = atomicAdd(&g_posu[u], 1);
    g_e2u[q] = make_int2(c, i);
}

// ---------------- GEMM A (frozen R13 config) ----------------
template <int OUTBF>
__global__ void __launch_bounds__(256) k_gemm(int aid, int bid,
                                              int K, int lda, int ldb, int ldc) {
    const bf16* A = hbufsel(aid);
    const bf16* Bt = hbufsel(bid);
    __shared__ bf16 As[2][128][40];
    __shared__ bf16 Bs[2][128][40];

    const int tid = threadIdx.x;
    const int warp = tid >> 5, lane = tid & 31;
    const int wm = (warp >> 2) << 6;
    const int wn = (warp & 3) << 5;
    const int bm = blockIdx.y << 7, bn = blockIdx.x << 7;
    const int lq = lane >> 2, lr = lane & 3;

    float c[4][4][4];
    #pragma unroll
    for (int i = 0; i < 4; i++)
        #pragma unroll
        for (int j = 0; j < 4; j++)
            #pragma unroll
            for (int e = 0; e < 4; e++) c[i][j][e] = 0.f;

    const int srow = tid >> 1;
    const int sch = (tid & 1) << 1;
    const bf16* aptr = A + (size_t)(bm + srow) * lda + sch * 8;
    const bf16* bptr = Bt + (size_t)(bn + srow) * ldb + sch * 8;

    const uint32_t asbase = smem_to_u32(&As[0][0][0]);
    const uint32_t bsbase = smem_to_u32(&Bs[0][0][0]);

    const int a_row = wm + ((lane >> 3) & 1) * 8 + (lane & 7);
    const int a_kb  = (lane >> 4) * 8;
    const int b_row = wn + (lane >> 4) * 8 + (lane & 7);
    const int b_kb  = ((lane >> 3) & 1) * 8;

    const int KT = K >> 5;
    uint4 ra0, ra1, rb0, rb1;

    ra0 = *(const uint4*)(aptr);
    ra1 = *(const uint4*)(aptr + 8);
    rb0 = *(const uint4*)(bptr);
    rb1 = *(const uint4*)(bptr + 8);
    *(uint4*)(&As[0][srow][sch * 8]) = ra0;
    *(uint4*)(&As[0][srow][sch * 8 + 8]) = ra1;
    *(uint4*)(&Bs[0][srow][sch * 8]) = rb0;
    *(uint4*)(&Bs[0][srow][sch * 8 + 8]) = rb1;
    __syncthreads();

    for (int kt = 0; kt < KT; kt++) {
        const int buf = kt & 1;
        if (kt + 1 < KT) {
            int k0 = (kt + 1) << 5;
            ra0 = *(const uint4*)(aptr + k0);
            ra1 = *(const uint4*)(aptr + k0 + 8);
            rb0 = *(const uint4*)(bptr + k0);
            rb1 = *(const uint4*)(bptr + k0 + 8);
        }
        #pragma unroll
        for (int ks = 0; ks < 2; ks++) {
            unsigned a[4][4], b[4][2];
            #pragma unroll
            for (int mt = 0; mt < 4; mt++) {
                uint32_t addr = asbase +
                    (uint32_t)(((buf * 128 + a_row + mt * 16) * 40 + ks * 16 + a_kb) * 2);
                ldsm_x4(a[mt][0], a[mt][1], a[mt][2], a[mt][3], addr);
            }
            #pragma unroll
            for (int np = 0; np < 2; np++) {
                uint32_t addr = bsbase +
                    (uint32_t)(((buf * 128 + b_row + np * 16) * 40 + ks * 16 + b_kb) * 2);
                ldsm_x4(b[np * 2][0], b[np * 2][1], b[np * 2 + 1][0], b[np * 2 + 1][1], addr);
            }
            #pragma unroll
            for (int mt = 0; mt < 4; mt++)
                #pragma unroll
                for (int nt = 0; nt < 4; nt++) mma_bf16(c[mt][nt], a[mt], b[nt]);
        }
        if (kt + 1 < KT) {
            const int nb = buf ^ 1;
            *(uint4*)(&As[nb][srow][sch * 8]) = ra0;
            *(uint4*)(&As[nb][srow][sch * 8 + 8]) = ra1;
            *(uint4*)(&Bs[nb][srow][sch * 8]) = rb0;
            *(uint4*)(&Bs[nb][srow][sch * 8 + 8]) = rb1;
            __syncthreads();
        }
    }

    #pragma unroll
    for (int mt = 0; mt < 4; mt++) {
        int row = bm + wm + (mt << 4) + lq;
        #pragma unroll
        for (int nt = 0; nt < 4; nt++) {
            int col = bn + wn + (nt << 3) + (lr << 1);
            if (OUTBF) {
                *(unsigned*)(g_Ph + (size_t)row * ldc + col) = f2h(c[mt][nt][0], c[mt][nt][1]);
                *(unsigned*)(g_Ph + (size_t)(row + 8) * ldc + col) = f2h(c[mt][nt][2], c[mt][nt][3]);
            } else {
                *(float2*)(g_gG + (size_t)row * ldc + col) = make_float2(c[mt][nt][0], c[mt][nt][1]);
                *(float2*)(g_gG + (size_t)(row + 8) * ldc + col) = make_float2(c[mt][nt][2], c[mt][nt][3]);
            }
        }
    }
}

// ---------------- GEMM B (frozen R12 config, for backward) ----------------
#define G2_SMEM 61440

template <int OUTBF>
__global__ void __launch_bounds__(256) k_gemm2(int aid, int bid,
                                               int K, int lda, int ldb, int ldc) {
    extern __shared__ __align__(16) bf16 smd[];
    bf16* As = smd;
    bf16* Bs = smd + 2 * 128 * 40;
    const bf16* A = hbufsel(aid);
    const bf16* Bt = hbufsel(bid);

    const int tid = threadIdx.x;
    const int warp = tid >> 5, lane = tid & 31;
    const int wm = (warp >> 2) << 6;
    const int wn = (warp & 3) << 6;
    const int bm = blockIdx.y << 7, bn = blockIdx.x << 8;
    const int lq = lane >> 2, lr = lane & 3;

    float c[4][8][4];
    #pragma unroll
    for (int i = 0; i < 4; i++)
        #pragma unroll
        for (int j = 0; j < 8; j++)
            #pragma unroll
            for (int e = 0; e < 4; e++) c[i][j][e] = 0.f;

    const int sarow = tid >> 1;
    const int sach = (tid & 1) << 1;
    const bf16* aptr = A + (size_t)(bm + sarow) * lda + sach * 8;
    const bf16* bptr = Bt + (size_t)(bn + tid) * ldb;

    const uint32_t asbase = smem_to_u32(As);
    const uint32_t bsbase = smem_to_u32(Bs);

    const int a_row = wm + ((lane >> 3) & 1) * 8 + (lane & 7);
    const int a_kb  = (lane >> 4) * 8;
    const int b_row = wn + (lane >> 4) * 8 + (lane & 7);
    const int b_kb  = ((lane >> 3) & 1) * 8;

    const int KT = K >> 5;
    uint4 pa0, pa1, pb0, pb1, pb2, pb3;

    pa0 = *(const uint4*)(aptr);
    pa1 = *(const uint4*)(aptr + 8);
    pb0 = *(const uint4*)(bptr);
    pb1 = *(const uint4*)(bptr + 8);
    pb2 = *(const uint4*)(bptr + 16);
    pb3 = *(const uint4*)(bptr + 24);
    *(uint4*)(As + sarow * 40 + sach * 8) = pa0;
    *(uint4*)(As + sarow * 40 + sach * 8 + 8) = pa1;
    *(uint4*)(Bs + tid * 40 + 0) = pb0;
    *(uint4*)(Bs + tid * 40 + 8) = pb1;
    *(uint4*)(Bs + tid * 40 + 16) = pb2;
    *(uint4*)(Bs + tid * 40 + 24) = pb3;
    __syncthreads();

    for (int kt = 0; kt < KT; kt++) {
        const int buf = kt & 1;
        if (kt + 1 < KT) {
            int k0 = (kt + 1) << 5;
            pa0 = *(const uint4*)(aptr + k0);
            pa1 = *(const uint4*)(aptr + k0 + 8);
            pb0 = *(const uint4*)(bptr + k0);
            pb1 = *(const uint4*)(bptr + k0 + 8);
            pb2 = *(const uint4*)(bptr + k0 + 16);
            pb3 = *(const uint4*)(bptr + k0 + 24);
        }
        #pragma unroll
        for (int ks = 0; ks < 2; ks++) {
            unsigned a[4][4], b[8][2];
            #pragma unroll
            for (int mt = 0; mt < 4; mt++) {
                uint32_t addr = asbase +
                    (uint32_t)(((buf * 128 + a_row + mt * 16) * 40 + ks * 16 + a_kb) * 2);
                ldsm_x4(a[mt][0], a[mt][1], a[mt][2], a[mt][3], addr);
            }
            #pragma unroll
            for (int np = 0; np < 4; np++) {
                uint32_t addr = bsbase +
                    (uint32_t)(((buf * 256 + b_row + np * 16) * 40 + ks * 16 + b_kb) * 2);
                ldsm_x4(b[np * 2][0], b[np * 2][1], b[np * 2 + 1][0], b[np * 2 + 1][1], addr);
            }
            #pragma unroll
            for (int mt = 0; mt < 4; mt++)
                #pragma unroll
                for (int nt = 0; nt < 8; nt++) mma_bf16(c[mt][nt], a[mt], b[nt]);
        }
        if (kt + 1 < KT) {
            const int nb = buf ^ 1;
            *(uint4*)(As + (nb * 128 + sarow) * 40 + sach * 8) = pa0;
            *(uint4*)(As + (nb * 128 + sarow) * 40 + sach * 8 + 8) = pa1;
            *(uint4*)(Bs + (nb * 256 + tid) * 40 + 0) = pb0;
            *(uint4*)(Bs + (nb * 256 + tid) * 40 + 8) = pb1;
            *(uint4*)(Bs + (nb * 256 + tid) * 40 + 16) = pb2;
            *(uint4*)(Bs + (nb * 256 + tid) * 40 + 24) = pb3;
            __syncthreads();
        }
    }

    #pragma unroll
    for (int mt = 0; mt < 4; mt++) {
        int row = bm + wm + (mt << 4) + lq;
        #pragma unroll
        for (int nt = 0; nt < 8; nt++) {
            int col = bn + wn + (nt << 3) + (lr << 1);
            if (OUTBF) {
                *(unsigned*)(g_Ph + (size_t)row * ldc + col) = f2h(c[mt][nt][0], c[mt][nt][1]);
                *(unsigned*)(g_Ph + (size_t)(row + 8) * ldc + col) = f2h(c[mt][nt][2], c[mt][nt][3]);
            } else {
                *(float2*)(g_gG + (size_t)row * ldc + col) = make_float2(c[mt][nt][0], c[mt][nt][1]);
                *(float2*)(g_gG + (size_t)(row + 8) * ldc + col) = make_float2(c[mt][nt][2], c[mt][nt][3]);
            }
        }
    }
}

// ---------------- device bodies for fused phase kernels ----------------
__device__ void edgeA_body(int c, int n, float* sl) {
    int lane = threadIdx.x & 31, wid = threadIdx.x >> 5;
    float lse = 0.f;
    if (c < n) {
        int beg = g_ofsc[c], end = g_ofsc[c + 1];
        float qf[8];
        unpack8(*(const uint4*)(g_Ph + (size_t)c * PS + OQ2 + lane * 8), qf);
        float se = 0.f;
        float acc[8];
        #pragma unroll
        for (int j = 0; j < 8; j++) acc[j] = 0.f;
        float sb2 = g_c.sb2;
        int2 pr0, pr1; uint4 kv0;
        if (beg < end) {
            pr0 = g_e2c[beg];
            if (beg + 1 < end) pr1 = g_e2c[beg + 1];
            kv0 = *(const uint4*)(g_Ph + (size_t)pr0.x * PS + OK2 + lane * 8);
        }
        for (int e = beg; e < end; e++) {
            int2 prn; uint4 kvn;
            if (e + 2 < end) prn = g_e2c[e + 2];
            if (e + 1 < end) kvn = *(const uint4*)(g_Ph + (size_t)pr1.x * PS + OK2 + lane * 8);
            float kf[8];
            unpack8(kv0, kf);
            float s = qf[0]*kf[0] + qf[1]*kf[1] + qf[2]*kf[2] + qf[3]*kf[3]
                    + qf[4]*kf[4] + qf[5]*kf[5] + qf[6]*kf[6] + qf[7]*kf[7];
            #pragma unroll
            for (int o = 16; o; o >>= 1) s += __shfl_xor_sync(0xffffffffu, s, o);
            float es = expf(s * sb2);
            if (!lane) g_S2[pr0.y] = es;
            se += es;
            #pragma unroll
            for (int j = 0; j < 8; j++) acc[j] = fmaf(es, kf[j], acc[j]);
            pr0 = pr1; pr1 = prn; kv0 = kvn;
        }
        uint4 o = make_uint4(0, 0, 0, 0);
        float invw = 0.f;
        if (end > beg) {
            lse = logf(se);
            invw = g_c.cw2 / se;
            o.x = f2h(acc[0] * invw, acc[1] * invw);
            o.y = f2h(acc[2] * invw, acc[3] * invw);
            o.z = f2h(acc[4] * invw, acc[5] * invw);
            o.w = f2h(acc[6] * invw, acc[7] * invw);
        }
        *(uint4*)(g_gPh + (size_t)c * PS + OQ2 + lane * 8) = o;
        if (!lane) g_LSE2[c] = invw;
    }
    if (!lane) sl[wid] = (c < n) ? lse : 0.f;
    __syncthreads();
    if (threadIdx.x == 0) {
        float t = 0.f;
        #pragma unroll
        for (int i = 0; i < 8; i++) t += sl[i];
        atomicAdd(&g_EL2, (double)t);
    }
}

__device__ void tri_dot_body(int gw, int nt,
                             const int* ci, const int* ui, const int* vi, const int* ti,
                             const float* T) {
    int lane = threadIdx.x & 31;
    if (gw >= nt) return;
    int c = ci[gw], u = ui[gw], v = vi[gw], tau = ti[gw];
    const uint4* q  = (const uint4*)(g_Ph + (size_t)c * PS + OQ3);
    const uint4* ku = (const uint4*)(g_Ph + (size_t)u * PS + OK3);
    const uint4* kv = (const uint4*)(g_Ph + (size_t)v * PS + OK3);
    const float4* tp = (const float4*)(T + (size_t)tau * RDm);
    float s = 0.f;
    #pragma unroll
    for (int f = 0; f < 2; f++) {
        int idx = lane + f * 32;
        float a[8], b[8], cc[8];
        unpack8(q[idx], a); unpack8(ku[idx], b); unpack8(kv[idx], cc);
        float4 t0 = tp[idx * 2], t1 = tp[idx * 2 + 1];
        s += a[0]*b[0]*cc[0]*t0.x + a[1]*b[1]*cc[1]*t0.y
           + a[2]*b[2]*cc[2]*t0.z + a[3]*b[3]*cc[3]*t0.w
           + a[4]*b[4]*cc[4]*t1.x + a[5]*b[5]*cc[5]*t1.y
           + a[6]*b[6]*cc[6]*t1.z + a[7]*b[7]*cc[7]*t1.w;
    }
    #pragma unroll
    for (int o = 16; o; o >>= 1) s += __shfl_xor_sync(0xffffffffu, s, o);
    if (!lane) {
        float es = expf(s * g_c.sb3);
        g_S3[gw] = es;
        atomicAdd(&g_ES3[c], es);
    }
}

__device__ void mem_body(int row, int n, float* sKm, float* sl) {
    int wid = threadIdx.x >> 5, lane = threadIdx.x & 31;
    for (int i = threadIdx.x; i < KSLOT * Dm; i += 256) sKm[i] = g_Km[i];
    __syncthreads();
    if (row >= n) return;
    float qf[8];
    unpack8(*(const uint4*)(g_Ph + (size_t)row * PS + OQm + lane * 8), qf);
    float myS = 0.f;
    float sbm = g_c.sbm;
    #pragma unroll
    for (int k0 = 0; k0 < KSLOT; k0 += 4) {
        float d[4];
        #pragma unroll
        for (int j = 0; j < 4; j++) {
            const float4* kp = (const float4*)(sKm + (k0 + j) * Dm + lane * 8);
            float4 a = kp[0], b = kp[1];
            d[j] = qf[0]*a.x + qf[1]*a.y + qf[2]*a.z + qf[3]*a.w
                 + qf[4]*b.x + qf[5]*b.y + qf[6]*b.z + qf[7]*b.w;
        }
        #pragma unroll
        for (int o = 16; o; o >>= 1) {
            #pragma unroll
            for (int j = 0; j < 4; j++) d[j] += __shfl_xor_sync(0xffffffffu, d[j], o);
        }
        #pragma unroll
        for (int j = 0; j < 4; j++)
            if (lane == k0 + j) myS = sbm * d[j];
    }
    float m = myS;
    #pragma unroll
    for (int o = 16; o; o >>= 1) m = fmaxf(m, __shfl_xor_sync(0xffffffffu, m, o));
    float e = expf(myS - m);
    #pragma unroll
    for (int o = 16; o; o >>= 1) e += __shfl_xor_sync(0xffffffffu, e, o);
    float lse = m + logf(e);
    float p = expf(myS - lse);
    float acc[8];
    #pragma unroll
    for (int j = 0; j < 8; j++) acc[j] = 0.f;
    #pragma unroll 4
    for (int k = 0; k < KSLOT; k++) {
        float pk = __shfl_sync(0xffffffffu, p, k);
        const float4* kp = (const float4*)(sKm + k * Dm + lane * 8);
        float4 k0 = kp[0], k1 = kp[1];
        acc[0] = fmaf(pk, k0.x, acc[0]); acc[1] = fmaf(pk, k0.y, acc[1]);
        acc[2] = fmaf(pk, k0.z, acc[2]); acc[3] = fmaf(pk, k0.w, acc[3]);
        acc[4] = fmaf(pk, k1.x, acc[4]); acc[5] = fmaf(pk, k1.y, acc[5]);
        acc[6] = fmaf(pk, k1.z, acc[6]); acc[7] = fmaf(pk, k1.w, acc[7]);
    }
    float cw = g_c.cwm;
    uint4 outv;
    outv.x = f2h(cw * acc[0], cw * acc[1]);
    outv.y = f2h(cw * acc[2], cw * acc[3]);
    outv.z = f2h(cw * acc[4], cw * acc[5]);
    outv.w = f2h(cw * acc[6], cw * acc[7]);
    *(uint4*)(g_gPh + (size_t)row * PS + OQm + lane * 8) = outv;
    if (!lane) sl[wid] = lse;
    __syncthreads();
    if (threadIdx.x == 0) {
        float t = 0.f;
        #pragma unroll
        for (int i = 0; i < 8; i++) t += sl[i];
        atomicAdd(&g_ELm, (double)t);
    }
}

// kB: interleaved {edgeA, tri_dot x2, mem} — grid = 4 * ceil(N/8)
__global__ void __launch_bounds__(256) kB(const int* __restrict__ ci, const int* __restrict__ ui,
                                          const int* __restrict__ vi, const int* __restrict__ ti,
                                          const float* __restrict__ T, int n, int nt) {
    __shared__ float sKm[KSLOT * Dm];
    __shared__ float sl[8];
    int g = blockIdx.x >> 2, r = blockIdx.x & 3;
    int wid = threadIdx.x >> 5;
    if (r == 0) {
        edgeA_body(g * 8 + wid, n, sl);
    } else if (r == 3) {
        mem_body(g * 8 + wid, n, sKm, sl);
    } else {
        tri_dot_body((2 * g + (r - 1)) * 8 + wid, nt, ci, ui, vi, ti, T);
    }
}

__device__ void edgeB_body(int u, int n) {
    int lane = threadIdx.x & 31;
    if (u >= n) return;
    int beg = g_ofsu[u], end = g_ofsu[u + 1];
    float acc[8];
    #pragma unroll
    for (int j = 0; j < 8; j++) acc[j] = 0.f;
    int2 pr0, pr1; uint4 qv0; float w0 = 0.f;
    if (beg < end) {
        pr0 = g_e2u[beg];
        if (beg + 1 < end) pr1 = g_e2u[beg + 1];
        qv0 = *(const uint4*)(g_Ph + (size_t)pr0.x * PS + OQ2 + lane * 8);
        w0 = g_S2[pr0.y] * g_LSE2[pr0.x];
    }
    for (int e = beg; e < end; e++) {
        int2 prn; uint4 qvn; float wn = 0.f;
        if (e + 2 < end) prn = g_e2u[e + 2];
        if (e + 1 < end) {
            qvn = *(const uint4*)(g_Ph + (size_t)pr1.x * PS + OQ2 + lane * 8);
            wn = g_S2[pr1.y] * g_LSE2[pr1.x];
        }
        float qf[8];
        unpack8(qv0, qf);
        #pragma unroll
        for (int j = 0; j < 8; j++) acc[j] = fmaf(w0, qf[j], acc[j]);
        pr0 = pr1; pr1 = prn; qv0 = qvn; w0 = wn;
    }
    uint4 o;
    o.x = f2h(acc[0], acc[1]);
    o.y = f2h(acc[2], acc[3]);
    o.z = f2h(acc[4], acc[5]);
    o.w = f2h(acc[6], acc[7]);
    *(uint4*)(g_gPh + (size_t)u * PS + OK2 + lane * 8) = o;
}

__device__ void tri_grad_body(int gw, int nt,
                              const int* ci, const int* ui, const int* vi, const int* ti,
                              const float* T) {
    int lane = threadIdx.x & 31;
    if (gw >= nt) return;
    int c = ci[gw], u = ui[gw], v = vi[gw], tau = ti[gw];
    float w = g_c.cw3 * g_S3[gw] / g_ES3[c];
    const uint4* q  = (const uint4*)(g_Ph + (size_t)c * PS + OQ3);
    const uint4* ku = (const uint4*)(g_Ph + (size_t)u * PS + OK3);
    const uint4* kv = (const uint4*)(g_Ph + (size_t)v * PS + OK3);
    const float4* tp = (const float4*)(T + (size_t)tau * RDm);
    #pragma unroll
    for (int f = 0; f < 2; f++) {
        int idx = lane + f * 32;
        float a[8], b[8], cc[8], t[8];
        unpack8(q[idx], a); unpack8(ku[idx], b); unpack8(kv[idx], cc);
        float4 t0 = tp[idx * 2], t1 = tp[idx * 2 + 1];
        t[0]=t0.x; t[1]=t0.y; t[2]=t0.z; t[3]=t0.w; t[4]=t1.x; t[5]=t1.y; t[6]=t1.z; t[7]=t1.w;
        float wt[8];
        #pragma unroll
        for (int j = 0; j < 8; j++) wt[j] = w * t[j];
        red16h(g_gPh + (size_t)c * PS + OQ3 + idx * 8,
               f2h(wt[0]*b[0]*cc[0], wt[1]*b[1]*cc[1]), f2h(wt[2]*b[2]*cc[2], wt[3]*b[3]*cc[3]),
               f2h(wt[4]*b[4]*cc[4], wt[5]*b[5]*cc[5]), f2h(wt[6]*b[6]*cc[6], wt[7]*b[7]*cc[7]));
        red16h(g_gPh + (size_t)u * PS + OK3 + idx * 8,
               f2h(wt[0]*a[0]*cc[0], wt[1]*a[1]*cc[1]), f2h(wt[2]*a[2]*cc[2], wt[3]*a[3]*cc[3]),
               f2h(wt[4]*a[4]*cc[4], wt[5]*a[5]*cc[5]), f2h(wt[6]*a[6]*cc[6], wt[7]*a[7]*cc[7]));
        red16h(g_gPh + (size_t)v * PS + OK3 + idx * 8,
               f2h(wt[0]*a[0]*b[0], wt[1]*a[1]*b[1]), f2h(wt[2]*a[2]*b[2], wt[3]*a[3]*b[3]),
               f2h(wt[4]*a[4]*b[4], wt[5]*a[5]*b[5]), f2h(wt[6]*a[6]*b[6], wt[7]*a[7]*b[7]));
    }
}

// kC: interleaved {edgeB, tri_grad x2} over 3*ceil(N/8), then seglse3 tail (128 blocks)
__global__ void __launch_bounds__(256) kC(const int* __restrict__ ci, const int* __restrict__ ui,
                                          const int* __restrict__ vi, const int* __restrict__ ti,
                                          const float* __restrict__ T, int n, int nt) {
    __shared__ float sb[8];
    int wid = threadIdx.x >> 5;
    int body = 3 * 4096;
    if ((int)blockIdx.x < body) {
        int g = blockIdx.x / 3, r = blockIdx.x % 3;
        if (r == 0) edgeB_body(g * 8 + wid, n);
        else tri_grad_body((2 * g + (r - 1)) * 8 + wid, nt, ci, ui, vi, ti, T);
        return;
    }
    // seglse3 energy tail
    int i = (blockIdx.x - body) * 256 + threadIdx.x;
    float lse = 0.f;
    if (i < n) {
        float es = g_ES3[i];
        if (es > 0.f) lse = logf(es);
    }
    float tot = blockSum256(lse, sb);
    if (threadIdx.x == 0) atomicAdd(&g_EL3, (double)tot);
}

__global__ void k_final(const float* __restrict__ X, const float* __restrict__ gamma,
                        float* __restrict__ out, int n, int out_size) {
    int row = blockIdx.x, t = threadIdx.x;
    __shared__ float sb[8];
    float rstd = g_rstd[row], mu = g_mu[row];
    float x = X[(size_t)row * Dm + t];
    float xh = (x - mu) * rstd;
    float gh = g_gG[(size_t)row * Dm + t] * gamma[t];
    float s1 = blockSum256(gh, sb) * (1.f / Dm);
    float s2 = blockSum256(gh * xh, sb) * (1.f / Dm);
    float gx = rstd * (gh - s1 - xh * s2);
    float gn2 = blockSum256(gx * gx, sb);
    float gn = fmaxf(sqrtf(gn2), 1e-6f);
    float fg = fminf(1.0f / gn, 1.0f);
    float xn = x - g_c.step * fg * gx;
    float sn2 = blockSum256(xn * xn, sb);
    float sn = fmaxf(sqrtf(sn2), 1e-6f);
    float fs = fminf(10.0f / sn, 1.0f);
    out[(size_t)row * Dm + t] = xn * fs;
    if (row == 0 && t == 0 && out_size > n * Dm) {
        double E = -((double)g_c.ce2 * g_EL2 + (double)g_c.ce3 * g_EL3 + (double)g_c.cem * g_ELm);
        out[(size_t)n * Dm] = (float)E;
    }
}

// ---------------- launch ----------------
extern "C" void kernel_launch(void* const* d_in, const int* in_sizes, int n_in,
                              void* d_out, int out_size) {
    const float* X     = (const float*)d_in[0];
    const int* c2      = (const int*)d_in[1];
    const int* u2      = (const int*)d_in[2];
    const int* c3      = (const int*)d_in[3];
    const int* u3      = (const int*)d_in[4];
    const int* v3      = (const int*)d_in[5];
    const int* ttau    = (const int*)d_in[6];
    const float* stepp = (const float*)d_in[7];
    const float* gamma = (const float*)d_in[8];
    const float* beta  = (const float*)d_in[9];
    const float* WQ2   = (const float*)d_in[10];
    const float* WK2   = (const float*)d_in[11];
    const float* WQ3   = (const float*)d_in[12];
    const float* WK3   = (const float*)d_in[13];
    const float* Ttau  = (const float*)d_in[14];
    const float* WQm   = (const float*)d_in[15];
    const float* WKm   = (const float*)d_in[16];
    const float* Bmem  = (const float*)d_in[17];
    const float* l2    = (const float*)d_in[18];
    const float* l3    = (const float*)d_in[19];
    const float* lm    = (const float*)d_in[20];
    const float* b2    = (const float*)d_in[21];
    const float* b3    = (const float*)d_in[22];
    const float* bm    = (const float*)d_in[23];
    float* out = (float*)d_out;

    int N  = in_sizes[0] / Dm;
    int ne = in_sizes[1];
    int nt = in_sizes[3];
    if (N > NMAX) N = NMAX;
    if (ne > NEMAX) ne = NEMAX;
    if (nt > NTMAX) nt = NTMAX;

    cudaFuncSetAttribute(k_gemm2<0>, cudaFuncAttributeMaxDynamicSharedMemorySize, G2_SMEM);

    // 1: fused setup (ln | pack | km | init+prep)
    kA<<<N + 1792 + 32 + 2048, 256>>>(X, gamma, beta, WQ2, WK2, WQm, WQ3, WK3,
                                      Bmem, WKm, l2, l3, lm, b2, b3, bm, stepp, N);
    // 2-3: CSR build (independent of GEMM)
    k_hist<<<(ne + 255) / 256, 256>>>(c2, u2, ne);
    k_scan<<<2, 1024>>>(N);
    // 4 (ncu-profiled slot): fused forward projection P = G @ Wf
    k_gemm<1><<<dim3(PS / 128, N / 128), 256>>>(0, 4, Dm, Dm, Dm, PS);
    // 5: CSR scatter
    k_scatter<<<(ne + 255) / 256, 256>>>(c2, u2, ne);
    // 6: fused phase 1 — edgeA | tri_dot | mem (interleaved)
    kB<<<4 * 4096, 256>>>(c3, u3, v3, ttau, Ttau, N, nt);
    // 7: fused phase 2 — edgeB | tri_grad (interleaved) + energy tail
    kC<<<3 * 4096 + 128, 256>>>(c3, u3, v3, ttau, Ttau, N, nt);
    // 8: fused backward projection: gG = gP @ Wf^T (K=1792)
    k_gemm2<0><<<dim3(Dm / 256, N / 128), 256, G2_SMEM>>>(2, 3, PS, PS, PS, Dm);
    // 9: LN backward + clip + update + clip + E
    k_final<<<N, 256>>>(X, gamma, out, N, out_size);
}

// round 17
// speedup vs baseline: 1.0866x; 1.0019x over previous
#include <cuda_runtime.h>
#include <cuda_bf16.h>
#include <cstdint>
#include <math.h>

#define Dm    256
#define NMAX  32768
#define NEMAX 1000000
#define NTMAX 65536
#define KSLOT 32
#define RDm   512
#define PS    1792   // packed row stride: Q2|K2|Qm|Q3|K3
#define OQ2   0
#define OK2   256
#define OQm   512
#define OQ3   768
#define OK3   1280

typedef __nv_bfloat16 bf16;
typedef __nv_bfloat162 bf162;

// ---------------- static device scratch ----------------
__device__ __align__(16) bf16  g_Gh[(size_t)NMAX * Dm];
__device__ __align__(16) bf16  g_Ph[(size_t)NMAX * PS];
__device__ __align__(16) bf16  g_gPh[(size_t)NMAX * PS];
__device__ __align__(16) bf16  g_Wfh[(size_t)Dm * PS];
__device__ __align__(16) bf16  g_Wbh[(size_t)PS * Dm];
__device__ __align__(16) float g_gG[(size_t)NMAX * Dm];
__device__ float g_mu[NMAX];
__device__ float g_rstd[NMAX];
__device__ float g_Km[KSLOT * Dm];
__device__ float g_S2[NEMAX];
__device__ float g_S3[NTMAX];
__device__ float g_ES3[NMAX];
__device__ float g_LSE2[NMAX];
__device__ double g_EL2, g_EL3, g_ELm;
__device__ int  g_cntc[NMAX], g_cntu[NMAX];
__device__ int  g_ofsc[NMAX + 1], g_ofsu[NMAX + 1];
__device__ int  g_posc[NMAX], g_posu[NMAX];
__device__ int2 g_e2c[NEMAX];
__device__ int2 g_e2u[NEMAX];

struct Consts {
    float sb2, sb3, sbm;
    float cw2, cw3, cwm;
    float ce2, ce3, cem;
    float step;
};
__device__ Consts g_c;

// ---------------- generic helpers ----------------
__device__ __forceinline__ float spf(float x) { return x > 20.f ? x : log1pf(expf(x)); }

__device__ __forceinline__ float2 h2f(unsigned u) {
    bf162 h = *(bf162*)&u;
    return __bfloat1622float2(h);
}
__device__ __forceinline__ unsigned f2h(float a, float b) {
    bf162 h = __floats2bfloat162_rn(a, b);
    return *(unsigned*)&h;
}
__device__ __forceinline__ void unpack8(uint4 v, float* f) {
    float2 p;
    p = h2f(v.x); f[0] = p.x; f[1] = p.y;
    p = h2f(v.y); f[2] = p.x; f[3] = p.y;
    p = h2f(v.z); f[4] = p.x; f[5] = p.y;
    p = h2f(v.w); f[6] = p.x; f[7] = p.y;
}

__device__ __forceinline__ void red16h(bf16* p, unsigned r0, unsigned r1, unsigned r2, unsigned r3) {
    asm volatile("red.global.add.noftz.v4.bf16x2 [%0], {%1,%2,%3,%4};"
                 :: "l"(__cvta_generic_to_global(p)), "r"(r0), "r"(r1), "r"(r2), "r"(r3)
                 : "memory");
}

__device__ __forceinline__ uint32_t smem_to_u32(const void* smem_ptr) {
    uint32_t addr;
    asm("{ .reg .u64 tmp; cvta.to.shared.u64 tmp, %1; cvt.u32.u64 %0, tmp; }"
        : "=r"(addr) : "l"(smem_ptr));
    return addr;
}

__device__ __forceinline__ void ldsm_x4(uint32_t& r0, uint32_t& r1, uint32_t& r2, uint32_t& r3,
                                        uint32_t addr) {
    asm volatile("ldmatrix.sync.aligned.m8n8.x4.shared.b16 {%0,%1,%2,%3}, [%4];"
                 : "=r"(r0), "=r"(r1), "=r"(r2), "=r"(r3) : "r"(addr));
}

__device__ __forceinline__ void mma_bf16(float c[4], const unsigned a[4], const unsigned b[2]) {
    asm volatile(
        "mma.sync.aligned.m16n8k16.row.col.f32.bf16.bf16.f32 "
        "{%0,%1,%2,%3},{%4,%5,%6,%7},{%8,%9},{%0,%1,%2,%3};"
        : "+f"(c[0]), "+f"(c[1]), "+f"(c[2]), "+f"(c[3])
        : "r"(a[0]), "r"(a[1]), "r"(a[2]), "r"(a[3]), "r"(b[0]), "r"(b[1]));
}

// cp.async helpers (sm_80+ base feature, legal under compute_103)
__device__ __forceinline__ void cpa16(uint32_t dst, const bf16* src) {
    asm volatile("cp.async.cg.shared.global [%0], [%1], 16;"
                 :: "r"(dst), "l"(__cvta_generic_to_global((const void*)src)) : "memory");
}
#define CPA_COMMIT() asm volatile("cp.async.commit_group;" ::: "memory")
#define CPA_WAIT0()  asm volatile("cp.async.wait_group 0;" ::: "memory")

__device__ __forceinline__ float blockSum256(float v, float* sbuf) {
    #pragma unroll
    for (int o = 16; o; o >>= 1) v += __shfl_xor_sync(0xffffffffu, v, o);
    int w = threadIdx.x >> 5;
    if ((threadIdx.x & 31) == 0) sbuf[w] = v;
    __syncthreads();
    if (threadIdx.x < 32) {
        float s = (threadIdx.x < 8) ? sbuf[threadIdx.x] : 0.f;
        #pragma unroll
        for (int o = 4; o; o >>= 1) s += __shfl_xor_sync(0xffffffffu, s, o);
        if (threadIdx.x == 0) sbuf[0] = s;
    }
    __syncthreads();
    float r = sbuf[0];
    __syncthreads();
    return r;
}

__device__ __forceinline__ const bf16* hbufsel(int id) {
    switch (id) {
        case 0:  return g_Gh;
        case 2:  return g_gPh;
        case 3:  return g_Wfh;
        default: return g_Wbh;
    }
}

// ================= fused setup kernel (kA) =================
__global__ void __launch_bounds__(256) kA(const float* __restrict__ X,
                                          const float* __restrict__ gamma,
                                          const float* __restrict__ beta,
                                          const float* __restrict__ WQ2,
                                          const float* __restrict__ WK2,
                                          const float* __restrict__ WQm,
                                          const float* __restrict__ WQ3,
                                          const float* __restrict__ WK3,
                                          const float* __restrict__ Bmem,
                                          const float* __restrict__ WKm,
                                          const float* l2, const float* l3, const float* lm,
                                          const float* b2p, const float* b3p, const float* bmp,
                                          const float* stepp, int n) {
    __shared__ float sb[8];
    int bid = blockIdx.x, t = threadIdx.x;
    if (bid < n) {
        int row = bid;
        float x = X[(size_t)row * Dm + t];
        float mu = blockSum256(x, sb) * (1.f / Dm);
        float d = x - mu;
        float var = blockSum256(d * d, sb) * (1.f / Dm);
        float rstd = rsqrtf(var + 1e-5f);
        if (t == 0) { g_mu[row] = mu; g_rstd[row] = rstd; }
        g_Gh[(size_t)row * Dm + t] = __float2bfloat16(d * rstd * gamma[t] + beta[t]);
        return;
    }
    bid -= n;
    if (bid < 1792) {
        int idx0 = bid * 256 + t;
        int k = idx0 / PS, nn = idx0 % PS;
        float w;
        if (nn < 256)       w = WQ2[k * 256 + nn];
        else if (nn < 512)  w = WK2[k * 256 + (nn - 256)];
        else if (nn < 768)  w = WQm[k * 256 + (nn - 512)];
        else if (nn < 1280) w = WQ3[k * 512 + (nn - 768)];
        else                w = WK3[k * 512 + (nn - 1280)];
        bf16 h = __float2bfloat16(w);
        g_Wfh[(size_t)k * PS + nn] = h;
        g_Wbh[(size_t)nn * Dm + k] = h;
        return;
    }
    bid -= 1792;
    if (bid < 32) {
        int k = bid, dcol = t;
        float acc = 0.f;
        for (int i = 0; i < Dm; i++) acc = fmaf(Bmem[k * Dm + i], WKm[i * Dm + dcol], acc);
        g_Km[k * Dm + dcol] = acc;
        return;
    }
    bid -= 32;
    if (bid == 0 && t == 0) {
        const float scale = 0.0625f;
        float lam2 = spf(*l2), lam3 = spf(*l3), lamm = spf(*lm);
        float b2 = fminf(spf(*b2p), 5.f);
        float b3 = fminf(spf(*b3p), 5.f);
        float bm = fminf(spf(*bmp), 5.f);
        g_c.sb2 = b2 * scale;    g_c.sb3 = b3 * scale;    g_c.sbm = bm * scale;
        g_c.cw2 = -lam2 * scale; g_c.cw3 = -lam3 * scale; g_c.cwm = -lamm * scale;
        g_c.ce2 = lam2 / b2;     g_c.ce3 = lam3 / b3;     g_c.cem = lamm / bm;
        g_c.step = (*stepp) * 0.9999f;
        g_EL2 = 0.0; g_EL3 = 0.0; g_ELm = 0.0;
    }
    size_t stride = (size_t)2048 * 256;
    size_t i0 = (size_t)bid * 256 + t;
    for (size_t i = i0; i < (size_t)n; i += stride) {
        g_cntc[i] = 0; g_cntu[i] = 0; g_ES3[i] = 0.f;
    }
    uint4 z = make_uint4(0, 0, 0, 0);
    size_t tot = (size_t)n * 128;
    for (size_t i = i0; i < tot; i += stride) {
        size_t row = i >> 7;
        size_t ch = i & 127;
        *(uint4*)(g_gPh + row * PS + OQ3 + ch * 8) = z;
    }
}

// ---------------- CSR build ----------------
__global__ void k_hist(const int* __restrict__ c2, const int* __restrict__ u2, int ne) {
    int i = blockIdx.x * blockDim.x + threadIdx.x;
    if (i >= ne) return;
    atomicAdd(&g_cntc[c2[i]], 1);
    atomicAdd(&g_cntu[u2[i]], 1);
}

__global__ void __launch_bounds__(1024) k_scan(int n) {
    int* cnt = blockIdx.x ? g_cntu : g_cntc;
    int* ofs = blockIdx.x ? g_ofsu : g_ofsc;
    int* pos = blockIdx.x ? g_posu : g_posc;
    __shared__ int sp[1024];
    int tid = threadIdx.x;
    int per = (n + 1023) / 1024;
    int b = tid * per;
    int s = 0;
    for (int j = 0; j < per; j++) if (b + j < n) s += cnt[b + j];
    sp[tid] = s;
    __syncthreads();
    int mine = s;
    for (int d = 1; d < 1024; d <<= 1) {
        int v = (tid >= d) ? sp[tid - d] : 0;
        __syncthreads();
        sp[tid] += v;
        __syncthreads();
    }
    int run = sp[tid] - mine;
    for (int j = 0; j < per; j++) {
        if (b + j < n) {
            ofs[b + j] = run;
            pos[b + j] = run;
            run += cnt[b + j];
        }
    }
    if (tid == 1023) ofs[n] = run;
}

__global__ void k_scatter(const int* __restrict__ c2, const int* __restrict__ u2, int ne) {
    int i = blockIdx.x * blockDim.x + threadIdx.x;
    if (i >= ne) return;
    int c = c2[i], u = u2[i];
    int p = atomicAdd(&g_posc[c], 1);
    g_e2c[p] = make_int2(u, i);
    int q = atomicAdd(&g_posu[u], 1);
    g_e2u[q] = make_int2(c, i);
}

// ---------------- GEMM A: 128x128 block, 8 warps, cp.async staging ----------------
template <int OUTBF>
__global__ void __launch_bounds__(256) k_gemm(int aid, int bid,
                                              int K, int lda, int ldb, int ldc) {
    const bf16* A = hbufsel(aid);
    const bf16* Bt = hbufsel(bid);
    __shared__ bf16 As[2][128][40];
    __shared__ bf16 Bs[2][128][40];

    const int tid = threadIdx.x;
    const int warp = tid >> 5, lane = tid & 31;
    const int wm = (warp >> 2) << 6;
    const int wn = (warp & 3) << 5;
    const int bm = blockIdx.y << 7, bn = blockIdx.x << 7;
    const int lq = lane >> 2, lr = lane & 3;

    float c[4][4][4];
    #pragma unroll
    for (int i = 0; i < 4; i++)
        #pragma unroll
        for (int j = 0; j < 4; j++)
            #pragma unroll
            for (int e = 0; e < 4; e++) c[i][j][e] = 0.f;

    const int srow = tid >> 1;
    const int sch = (tid & 1) << 1;
    const bf16* aptr = A + (size_t)(bm + srow) * lda + sch * 8;
    const bf16* bptr = Bt + (size_t)(bn + srow) * ldb + sch * 8;

    const uint32_t asbase = smem_to_u32(&As[0][0][0]);
    const uint32_t bsbase = smem_to_u32(&Bs[0][0][0]);
    const uint32_t stoff = (uint32_t)((srow * 40 + sch * 8) * 2);

    const int a_row = wm + ((lane >> 3) & 1) * 8 + (lane & 7);
    const int a_kb  = (lane >> 4) * 8;
    const int b_row = wn + (lane >> 4) * 8 + (lane & 7);
    const int b_kb  = ((lane >> 3) & 1) * 8;

    const int KT = K >> 5;

    cpa16(asbase + stoff, aptr);
    cpa16(asbase + stoff + 16, aptr + 8);
    cpa16(bsbase + stoff, bptr);
    cpa16(bsbase + stoff + 16, bptr + 8);
    CPA_COMMIT();
    CPA_WAIT0();
    __syncthreads();

    for (int kt = 0; kt < KT; kt++) {
        const int buf = kt & 1;
        if (kt + 1 < KT) {
            int k0 = (kt + 1) << 5;
            uint32_t nboff = (uint32_t)(((kt + 1) & 1) * 128 * 40 * 2) + stoff;
            cpa16(asbase + nboff, aptr + k0);
            cpa16(asbase + nboff + 16, aptr + k0 + 8);
            cpa16(bsbase + nboff, bptr + k0);
            cpa16(bsbase + nboff + 16, bptr + k0 + 8);
            CPA_COMMIT();
        }
        #pragma unroll
        for (int ks = 0; ks < 2; ks++) {
            unsigned a[4][4], b[4][2];
            #pragma unroll
            for (int mt = 0; mt < 4; mt++) {
                uint32_t addr = asbase +
                    (uint32_t)(((buf * 128 + a_row + mt * 16) * 40 + ks * 16 + a_kb) * 2);
                ldsm_x4(a[mt][0], a[mt][1], a[mt][2], a[mt][3], addr);
            }
            #pragma unroll
            for (int np = 0; np < 2; np++) {
                uint32_t addr = bsbase +
                    (uint32_t)(((buf * 128 + b_row + np * 16) * 40 + ks * 16 + b_kb) * 2);
                ldsm_x4(b[np * 2][0], b[np * 2][1], b[np * 2 + 1][0], b[np * 2 + 1][1], addr);
            }
            #pragma unroll
            for (int mt = 0; mt < 4; mt++)
                #pragma unroll
                for (int nt = 0; nt < 4; nt++) mma_bf16(c[mt][nt], a[mt], b[nt]);
        }
        if (kt + 1 < KT) {
            CPA_WAIT0();
            __syncthreads();
        }
    }

    #pragma unroll
    for (int mt = 0; mt < 4; mt++) {
        int row = bm + wm + (mt << 4) + lq;
        #pragma unroll
        for (int nt = 0; nt < 4; nt++) {
            int col = bn + wn + (nt << 3) + (lr << 1);
            if (OUTBF) {
                *(unsigned*)(g_Ph + (size_t)row * ldc + col) = f2h(c[mt][nt][0], c[mt][nt][1]);
                *(unsigned*)(g_Ph + (size_t)(row + 8) * ldc + col) = f2h(c[mt][nt][2], c[mt][nt][3]);
            } else {
                *(float2*)(g_gG + (size_t)row * ldc + col) = make_float2(c[mt][nt][0], c[mt][nt][1]);
                *(float2*)(g_gG + (size_t)(row + 8) * ldc + col) = make_float2(c[mt][nt][2], c[mt][nt][3]);
            }
        }
    }
}

// ---------------- GEMM B: 128x256 block, 8 warps, cp.async staging ----------------
#define G2_SMEM 61440

template <int OUTBF>
__global__ void __launch_bounds__(256) k_gemm2(int aid, int bid,
                                               int K, int lda, int ldb, int ldc) {
    extern __shared__ __align__(16) bf16 smd[];
    bf16* As = smd;
    bf16* Bs = smd + 2 * 128 * 40;
    const bf16* A = hbufsel(aid);
    const bf16* Bt = hbufsel(bid);

    const int tid = threadIdx.x;
    const int warp = tid >> 5, lane = tid & 31;
    const int wm = (warp >> 2) << 6;
    const int wn = (warp & 3) << 6;
    const int bm = blockIdx.y << 7, bn = blockIdx.x << 8;
    const int lq = lane >> 2, lr = lane & 3;

    float c[4][8][4];
    #pragma unroll
    for (int i = 0; i < 4; i++)
        #pragma unroll
        for (int j = 0; j < 8; j++)
            #pragma unroll
            for (int e = 0; e < 4; e++) c[i][j][e] = 0.f;

    const int sarow = tid >> 1;
    const int sach = (tid & 1) << 1;
    const bf16* aptr = A + (size_t)(bm + sarow) * lda + sach * 8;
    const bf16* bptr = Bt + (size_t)(bn + tid) * ldb;

    const uint32_t asbase = smem_to_u32(As);
    const uint32_t bsbase = smem_to_u32(Bs);
    const uint32_t astoff = (uint32_t)((sarow * 40 + sach * 8) * 2);
    const uint32_t bstoff = (uint32_t)((tid * 40) * 2);

    const int a_row = wm + ((lane >> 3) & 1) * 8 + (lane & 7);
    const int a_kb  = (lane >> 4) * 8;
    const int b_row = wn + (lane >> 4) * 8 + (lane & 7);
    const int b_kb  = ((lane >> 3) & 1) * 8;

    const int KT = K >> 5;

    cpa16(asbase + astoff, aptr);
    cpa16(asbase + astoff + 16, aptr + 8);
    cpa16(bsbase + bstoff, bptr);
    cpa16(bsbase + bstoff + 16, bptr + 8);
    cpa16(bsbase + bstoff + 32, bptr + 16);
    cpa16(bsbase + bstoff + 48, bptr + 24);
    CPA_COMMIT();
    CPA_WAIT0();
    __syncthreads();

    for (int kt = 0; kt < KT; kt++) {
        const int buf = kt & 1;
        if (kt + 1 < KT) {
            int k0 = (kt + 1) << 5;
            int nb = (kt + 1) & 1;
            uint32_t an = asbase + (uint32_t)(nb * 128 * 40 * 2) + astoff;
            uint32_t bn2 = bsbase + (uint32_t)(nb * 256 * 40 * 2) + bstoff;
            cpa16(an, aptr + k0);
            cpa16(an + 16, aptr + k0 + 8);
            cpa16(bn2, bptr + k0);
            cpa16(bn2 + 16, bptr + k0 + 8);
            cpa16(bn2 + 32, bptr + k0 + 16);
            cpa16(bn2 + 48, bptr + k0 + 24);
            CPA_COMMIT();
        }
        #pragma unroll
        for (int ks = 0; ks < 2; ks++) {
            unsigned a[4][4], b[8][2];
            #pragma unroll
            for (int mt = 0; mt < 4; mt++) {
                uint32_t addr = asbase +
                    (uint32_t)(((buf * 128 + a_row + mt * 16) * 40 + ks * 16 + a_kb) * 2);
                ldsm_x4(a[mt][0], a[mt][1], a[mt][2], a[mt][3], addr);
            }
            #pragma unroll
            for (int np = 0; np < 4; np++) {
                uint32_t addr = bsbase +
                    (uint32_t)(((buf * 256 + b_row + np * 16) * 40 + ks * 16 + b_kb) * 2);
                ldsm_x4(b[np * 2][0], b[np * 2][1], b[np * 2 + 1][0], b[np * 2 + 1][1], addr);
            }
            #pragma unroll
            for (int mt = 0; mt < 4; mt++)
                #pragma unroll
                for (int nt = 0; nt < 8; nt++) mma_bf16(c[mt][nt], a[mt], b[nt]);
        }
        if (kt + 1 < KT) {
            CPA_WAIT0();
            __syncthreads();
        }
    }

    #pragma unroll
    for (int mt = 0; mt < 4; mt++) {
        int row = bm + wm + (mt << 4) + lq;
        #pragma unroll
        for (int nt = 0; nt < 8; nt++) {
            int col = bn + wn + (nt << 3) + (lr << 1);
            if (OUTBF) {
                *(unsigned*)(g_Ph + (size_t)row * ldc + col) = f2h(c[mt][nt][0], c[mt][nt][1]);
                *(unsigned*)(g_Ph + (size_t)(row + 8) * ldc + col) = f2h(c[mt][nt][2], c[mt][nt][3]);
            } else {
                *(float2*)(g_gG + (size_t)row * ldc + col) = make_float2(c[mt][nt][0], c[mt][nt][1]);
                *(float2*)(g_gG + (size_t)(row + 8) * ldc + col) = make_float2(c[mt][nt][2], c[mt][nt][3]);
            }
        }
    }
}

// ---------------- device bodies for fused phase kernels ----------------
__device__ void edgeA_body(int c, int n, float* sl) {
    int lane = threadIdx.x & 31, wid = threadIdx.x >> 5;
    float lse = 0.f;
    if (c < n) {
        int beg = g_ofsc[c], end = g_ofsc[c + 1];
        float qf[8];
        unpack8(*(const uint4*)(g_Ph + (size_t)c * PS + OQ2 + lane * 8), qf);
        float se = 0.f;
        float acc[8];
        #pragma unroll
        for (int j = 0; j < 8; j++) acc[j] = 0.f;
        float sb2 = g_c.sb2;
        int2 pr0, pr1; uint4 kv0;
        if (beg < end) {
            pr0 = g_e2c[beg];
            if (beg + 1 < end) pr1 = g_e2c[beg + 1];
            kv0 = *(const uint4*)(g_Ph + (size_t)pr0.x * PS + OK2 + lane * 8);
        }
        for (int e = beg; e < end; e++) {
            int2 prn; uint4 kvn;
            if (e + 2 < end) prn = g_e2c[e + 2];
            if (e + 1 < end) kvn = *(const uint4*)(g_Ph + (size_t)pr1.x * PS + OK2 + lane * 8);
            float kf[8];
            unpack8(kv0, kf);
            float s = qf[0]*kf[0] + qf[1]*kf[1] + qf[2]*kf[2] + qf[3]*kf[3]
                    + qf[4]*kf[4] + qf[5]*kf[5] + qf[6]*kf[6] + qf[7]*kf[7];
            #pragma unroll
            for (int o = 16; o; o >>= 1) s += __shfl_xor_sync(0xffffffffu, s, o);
            float es = expf(s * sb2);
            if (!lane) g_S2[pr0.y] = es;
            se += es;
            #pragma unroll
            for (int j = 0; j < 8; j++) acc[j] = fmaf(es, kf[j], acc[j]);
            pr0 = pr1; pr1 = prn; kv0 = kvn;
        }
        uint4 o = make_uint4(0, 0, 0, 0);
        float invw = 0.f;
        if (end > beg) {
            lse = logf(se);
            invw = g_c.cw2 / se;
            o.x = f2h(acc[0] * invw, acc[1] * invw);
            o.y = f2h(acc[2] * invw, acc[3] * invw);
            o.z = f2h(acc[4] * invw, acc[5] * invw);
            o.w = f2h(acc[6] * invw, acc[7] * invw);
        }
        *(uint4*)(g_gPh + (size_t)c * PS + OQ2 + lane * 8) = o;
        if (!lane) g_LSE2[c] = invw;
    }
    if (!lane) sl[wid] = (c < n) ? lse : 0.f;
    __syncthreads();
    if (threadIdx.x == 0) {
        float t = 0.f;
        #pragma unroll
        for (int i = 0; i < 8; i++) t += sl[i];
        atomicAdd(&g_EL2, (double)t);
    }
}

__device__ void tri_dot_body(int gw, int nt,
                             const int* ci, const int* ui, const int* vi, const int* ti,
                             const float* T) {
    int lane = threadIdx.x & 31;
    if (gw >= nt) return;
    int c = ci[gw], u = ui[gw], v = vi[gw], tau = ti[gw];
    const uint4* q  = (const uint4*)(g_Ph + (size_t)c * PS + OQ3);
    const uint4* ku = (const uint4*)(g_Ph + (size_t)u * PS + OK3);
    const uint4* kv = (const uint4*)(g_Ph + (size_t)v * PS + OK3);
    const float4* tp = (const float4*)(T + (size_t)tau * RDm);
    float s = 0.f;
    #pragma unroll
    for (int f = 0; f < 2; f++) {
        int idx = lane + f * 32;
        float a[8], b[8], cc[8];
        unpack8(q[idx], a); unpack8(ku[idx], b); unpack8(kv[idx], cc);
        float4 t0 = tp[idx * 2], t1 = tp[idx * 2 + 1];
        s += a[0]*b[0]*cc[0]*t0.x + a[1]*b[1]*cc[1]*t0.y
           + a[2]*b[2]*cc[2]*t0.z + a[3]*b[3]*cc[3]*t0.w
           + a[4]*b[4]*cc[4]*t1.x + a[5]*b[5]*cc[5]*t1.y
           + a[6]*b[6]*cc[6]*t1.z + a[7]*b[7]*cc[7]*t1.w;
    }
    #pragma unroll
    for (int o = 16; o; o >>= 1) s += __shfl_xor_sync(0xffffffffu, s, o);
    if (!lane) {
        float es = expf(s * g_c.sb3);
        g_S3[gw] = es;
        atomicAdd(&g_ES3[c], es);
    }
}

__device__ void mem_body(int row, int n, float* sKm, float* sl) {
    int wid = threadIdx.x >> 5, lane = threadIdx.x & 31;
    for (int i = threadIdx.x; i < KSLOT * Dm; i += 256) sKm[i] = g_Km[i];
    __syncthreads();
    if (row >= n) return;
    float qf[8];
    unpack8(*(const uint4*)(g_Ph + (size_t)row * PS + OQm + lane * 8), qf);
    float myS = 0.f;
    float sbm = g_c.sbm;
    #pragma unroll
    for (int k0 = 0; k0 < KSLOT; k0 += 4) {
        float d[4];
        #pragma unroll
        for (int j = 0; j < 4; j++) {
            const float4* kp = (const float4*)(sKm + (k0 + j) * Dm + lane * 8);
            float4 a = kp[0], b = kp[1];
            d[j] = qf[0]*a.x + qf[1]*a.y + qf[2]*a.z + qf[3]*a.w
                 + qf[4]*b.x + qf[5]*b.y + qf[6]*b.z + qf[7]*b.w;
        }
        #pragma unroll
        for (int o = 16; o; o >>= 1) {
            #pragma unroll
            for (int j = 0; j < 4; j++) d[j] += __shfl_xor_sync(0xffffffffu, d[j], o);
        }
        #pragma unroll
        for (int j = 0; j < 4; j++)
            if (lane == k0 + j) myS = sbm * d[j];
    }
    float m = myS;
    #pragma unroll
    for (int o = 16; o; o >>= 1) m = fmaxf(m, __shfl_xor_sync(0xffffffffu, m, o));
    float e = expf(myS - m);
    #pragma unroll
    for (int o = 16; o; o >>= 1) e += __shfl_xor_sync(0xffffffffu, e, o);
    float lse = m + logf(e);
    float p = expf(myS - lse);
    float acc[8];
    #pragma unroll
    for (int j = 0; j < 8; j++) acc[j] = 0.f;
    #pragma unroll 4
    for (int k = 0; k < KSLOT; k++) {
        float pk = __shfl_sync(0xffffffffu, p, k);
        const float4* kp = (const float4*)(sKm + k * Dm + lane * 8);
        float4 k0 = kp[0], k1 = kp[1];
        acc[0] = fmaf(pk, k0.x, acc[0]); acc[1] = fmaf(pk, k0.y, acc[1]);
        acc[2] = fmaf(pk, k0.z, acc[2]); acc[3] = fmaf(pk, k0.w, acc[3]);
        acc[4] = fmaf(pk, k1.x, acc[4]); acc[5] = fmaf(pk, k1.y, acc[5]);
        acc[6] = fmaf(pk, k1.z, acc[6]); acc[7] = fmaf(pk, k1.w, acc[7]);
    }
    float cw = g_c.cwm;
    uint4 outv;
    outv.x = f2h(cw * acc[0], cw * acc[1]);
    outv.y = f2h(cw * acc[2], cw * acc[3]);
    outv.z = f2h(cw * acc[4], cw * acc[5]);
    outv.w = f2h(cw * acc[6], cw * acc[7]);
    *(uint4*)(g_gPh + (size_t)row * PS + OQm + lane * 8) = outv;
    if (!lane) sl[wid] = lse;
    __syncthreads();
    if (threadIdx.x == 0) {
        float t = 0.f;
        #pragma unroll
        for (int i = 0; i < 8; i++) t += sl[i];
        atomicAdd(&g_ELm, (double)t);
    }
}

__global__ void __launch_bounds__(256) kB(const int* __restrict__ ci, const int* __restrict__ ui,
                                          const int* __restrict__ vi, const int* __restrict__ ti,
                                          const float* __restrict__ T, int n, int nt) {
    __shared__ float sKm[KSLOT * Dm];
    __shared__ float sl[8];
    int g = blockIdx.x >> 2, r = blockIdx.x & 3;
    int wid = threadIdx.x >> 5;
    if (r == 0) {
        edgeA_body(g * 8 + wid, n, sl);
    } else if (r == 3) {
        mem_body(g * 8 + wid, n, sKm, sl);
    } else {
        tri_dot_body((2 * g + (r - 1)) * 8 + wid, nt, ci, ui, vi, ti, T);
    }
}

__device__ void edgeB_body(int u, int n) {
    int lane = threadIdx.x & 31;
    if (u >= n) return;
    int beg = g_ofsu[u], end = g_ofsu[u + 1];
    float acc[8];
    #pragma unroll
    for (int j = 0; j < 8; j++) acc[j] = 0.f;
    int2 pr0, pr1; uint4 qv0; float w0 = 0.f;
    if (beg < end) {
        pr0 = g_e2u[beg];
        if (beg + 1 < end) pr1 = g_e2u[beg + 1];
        qv0 = *(const uint4*)(g_Ph + (size_t)pr0.x * PS + OQ2 + lane * 8);
        w0 = g_S2[pr0.y] * g_LSE2[pr0.x];
    }
    for (int e = beg; e < end; e++) {
        int2 prn; uint4 qvn; float wn = 0.f;
        if (e + 2 < end) prn = g_e2u[e + 2];
        if (e + 1 < end) {
            qvn = *(const uint4*)(g_Ph + (size_t)pr1.x * PS + OQ2 + lane * 8);
            wn = g_S2[pr1.y] * g_LSE2[pr1.x];
        }
        float qf[8];
        unpack8(qv0, qf);
        #pragma unroll
        for (int j = 0; j < 8; j++) acc[j] = fmaf(w0, qf[j], acc[j]);
        pr0 = pr1; pr1 = prn; qv0 = qvn; w0 = wn;
    }
    uint4 o;
    o.x = f2h(acc[0], acc[1]);
    o.y = f2h(acc[2], acc[3]);
    o.z = f2h(acc[4], acc[5]);
    o.w = f2h(acc[6], acc[7]);
    *(uint4*)(g_gPh + (size_t)u * PS + OK2 + lane * 8) = o;
}

__device__ void tri_grad_body(int gw, int nt,
                              const int* ci, const int* ui, const int* vi, const int* ti,
                              const float* T) {
    int lane = threadIdx.x & 31;
    if (gw >= nt) return;
    int c = ci[gw], u = ui[gw], v = vi[gw], tau = ti[gw];
    float w = g_c.cw3 * g_S3[gw] / g_ES3[c];
    const uint4* q  = (const uint4*)(g_Ph + (size_t)c * PS + OQ3);
    const uint4* ku = (const uint4*)(g_Ph + (size_t)u * PS + OK3);
    const uint4* kv = (const uint4*)(g_Ph + (size_t)v * PS + OK3);
    const float4* tp = (const float4*)(T + (size_t)tau * RDm);
    #pragma unroll
    for (int f = 0; f < 2; f++) {
        int idx = lane + f * 32;
        float a[8], b[8], cc[8], t[8];
        unpack8(q[idx], a); unpack8(ku[idx], b); unpack8(kv[idx], cc);
        float4 t0 = tp[idx * 2], t1 = tp[idx * 2 + 1];
        t[0]=t0.x; t[1]=t0.y; t[2]=t0.z; t[3]=t0.w; t[4]=t1.x; t[5]=t1.y; t[6]=t1.z; t[7]=t1.w;
        float wt[8];
        #pragma unroll
        for (int j = 0; j < 8; j++) wt[j] = w * t[j];
        red16h(g_gPh + (size_t)c * PS + OQ3 + idx * 8,
               f2h(wt[0]*b[0]*cc[0], wt[1]*b[1]*cc[1]), f2h(wt[2]*b[2]*cc[2], wt[3]*b[3]*cc[3]),
               f2h(wt[4]*b[4]*cc[4], wt[5]*b[5]*cc[5]), f2h(wt[6]*b[6]*cc[6], wt[7]*b[7]*cc[7]));
        red16h(g_gPh + (size_t)u * PS + OK3 + idx * 8,
               f2h(wt[0]*a[0]*cc[0], wt[1]*a[1]*cc[1]), f2h(wt[2]*a[2]*cc[2], wt[3]*a[3]*cc[3]),
               f2h(wt[4]*a[4]*cc[4], wt[5]*a[5]*cc[5]), f2h(wt[6]*a[6]*cc[6], wt[7]*a[7]*cc[7]));
        red16h(g_gPh + (size_t)v * PS + OK3 + idx * 8,
               f2h(wt[0]*a[0]*b[0], wt[1]*a[1]*b[1]), f2h(wt[2]*a[2]*b[2], wt[3]*a[3]*b[3]),
               f2h(wt[4]*a[4]*b[4], wt[5]*a[5]*b[5]), f2h(wt[6]*a[6]*b[6], wt[7]*a[7]*b[7]));
    }
}

__global__ void __launch_bounds__(256) kC(const int* __restrict__ ci, const int* __restrict__ ui,
                                          const int* __restrict__ vi, const int* __restrict__ ti,
                                          const float* __restrict__ T, int n, int nt) {
    __shared__ float sb[8];
    int wid = threadIdx.x >> 5;
    int body = 3 * 4096;
    if ((int)blockIdx.x < body) {
        int g = blockIdx.x / 3, r = blockIdx.x % 3;
        if (r == 0) edgeB_body(g * 8 + wid, n);
        else tri_grad_body((2 * g + (r - 1)) * 8 + wid, nt, ci, ui, vi, ti, T);
        return;
    }
    int i = (blockIdx.x - body) * 256 + threadIdx.x;
    float lse = 0.f;
    if (i < n) {
        float es = g_ES3[i];
        if (es > 0.f) lse = logf(es);
    }
    float tot = blockSum256(lse, sb);
    if (threadIdx.x == 0) atomicAdd(&g_EL3, (double)tot);
}

__global__ void k_final(const float* __restrict__ X, const float* __restrict__ gamma,
                        float* __restrict__ out, int n, int out_size) {
    int row = blockIdx.x, t = threadIdx.x;
    __shared__ float sb[8];
    float rstd = g_rstd[row], mu = g_mu[row];
    float x = X[(size_t)row * Dm + t];
    float xh = (x - mu) * rstd;
    float gh = g_gG[(size_t)row * Dm + t] * gamma[t];
    float s1 = blockSum256(gh, sb) * (1.f / Dm);
    float s2 = blockSum256(gh * xh, sb) * (1.f / Dm);
    float gx = rstd * (gh - s1 - xh * s2);
    float gn2 = blockSum256(gx * gx, sb);
    float gn = fmaxf(sqrtf(gn2), 1e-6f);
    float fg = fminf(1.0f / gn, 1.0f);
    float xn = x - g_c.step * fg * gx;
    float sn2 = blockSum256(xn * xn, sb);
    float sn = fmaxf(sqrtf(sn2), 1e-6f);
    float fs = fminf(10.0f / sn, 1.0f);
    out[(size_t)row * Dm + t] = xn * fs;
    if (row == 0 && t == 0 && out_size > n * Dm) {
        double E = -((double)g_c.ce2 * g_EL2 + (double)g_c.ce3 * g_EL3 + (double)g_c.cem * g_ELm);
        out[(size_t)n * Dm] = (float)E;
    }
}

// ---------------- launch ----------------
extern "C" void kernel_launch(void* const* d_in, const int* in_sizes, int n_in,
                              void* d_out, int out_size) {
    const float* X     = (const float*)d_in[0];
    const int* c2      = (const int*)d_in[1];
    const int* u2      = (const int*)d_in[2];
    const int* c3      = (const int*)d_in[3];
    const int* u3      = (const int*)d_in[4];
    const int* v3      = (const int*)d_in[5];
    const int* ttau    = (const int*)d_in[6];
    const float* stepp = (const float*)d_in[7];
    const float* gamma = (const float*)d_in[8];
    const float* beta  = (const float*)d_in[9];
    const float* WQ2   = (const float*)d_in[10];
    const float* WK2   = (const float*)d_in[11];
    const float* WQ3   = (const float*)d_in[12];
    const float* WK3   = (const float*)d_in[13];
    const float* Ttau  = (const float*)d_in[14];
    const float* WQm   = (const float*)d_in[15];
    const float* WKm   = (const float*)d_in[16];
    const float* Bmem  = (const float*)d_in[17];
    const float* l2    = (const float*)d_in[18];
    const float* l3    = (const float*)d_in[19];
    const float* lm    = (const float*)d_in[20];
    const float* b2    = (const float*)d_in[21];
    const float* b3    = (const float*)d_in[22];
    const float* bm    = (const float*)d_in[23];
    float* out = (float*)d_out;

    int N  = in_sizes[0] / Dm;
    int ne = in_sizes[1];
    int nt = in_sizes[3];
    if (N > NMAX) N = NMAX;
    if (ne > NEMAX) ne = NEMAX;
    if (nt > NTMAX) nt = NTMAX;

    cudaFuncSetAttribute(k_gemm2<0>, cudaFuncAttributeMaxDynamicSharedMemorySize, G2_SMEM);

    // side stream + fork/join events (host objects; capture-legal pattern)
    cudaStream_t s2;
    cudaStreamCreateWithFlags(&s2, cudaStreamNonBlocking);
    cudaEvent_t e1, e2;
    cudaEventCreateWithFlags(&e1, cudaEventDisableTiming);
    cudaEventCreateWithFlags(&e2, cudaEventDisableTiming);

    // 1: fused setup (ln | pack | km | init+prep)
    kA<<<N + 1792 + 32 + 2048, 256>>>(X, gamma, beta, WQ2, WK2, WQm, WQ3, WK3,
                                      Bmem, WKm, l2, l3, lm, b2, b3, bm, stepp, N);
    // fork: CSR build on side stream, overlapping the forward GEMM
    cudaEventRecord(e1, 0);
    cudaStreamWaitEvent(s2, e1, 0);
    k_hist<<<(ne + 255) / 256, 256, 0, s2>>>(c2, u2, ne);
    k_scan<<<2, 1024, 0, s2>>>(N);
    k_scatter<<<(ne + 255) / 256, 256, 0, s2>>>(c2, u2, ne);
    cudaEventRecord(e2, s2);

    // forward projection P = G @ Wf on main stream (overlaps CSR build)
    k_gemm<1><<<dim3(PS / 128, N / 128), 256>>>(0, 4, Dm, Dm, Dm, PS);

    // join
    cudaStreamWaitEvent(0, e2, 0);

    // fused phase 1 — edgeA | tri_dot | mem (interleaved)
    kB<<<4 * 4096, 256>>>(c3, u3, v3, ttau, Ttau, N, nt);
    // fused phase 2 — edgeB | tri_grad (interleaved) + energy tail
    kC<<<3 * 4096 + 128, 256>>>(c3, u3, v3, ttau, Ttau, N, nt);
    // fused backward projection: gG = gP @ Wf^T (K=1792)
    k_gemm2<0><<<dim3(Dm / 256, N / 128), 256, G2_SMEM>>>(2, 3, PS, PS, PS, Dm);
    // LN backward + clip + update + clip + E
    k_final<<<N, 256>>>(X, gamma, out, N, out_size);

    cudaEventDestroy(e1);
    cudaEventDestroy(e2);
    cudaStreamDestroy(s2);
}